// round 1
// baseline (speedup 1.0000x reference)
#include <cuda_runtime.h>
#include <cstdint>

#define B_   2048
#define T_   200
#define F_   64
#define H_   128
#define IN_  256
#define K_   384   // IN + H
#define G_   384   // 3H
#define BR   16    // batch rows per block
#define NT   128   // threads per block (one per hidden unit j)
#define NB   (B_/BR)
#define UPITCH 18  // floats per k-row of u: 8 row-pairs (float2) + 1 pad pair

typedef unsigned long long u64;

// ---------- packed weights (built by prep kernel each launch) ----------
__device__ float g_Wt4[(K_/4)*G_*4];   // [k4][c][ks] : Wfull[c][4k4+ks]
__device__ float g_Wdh4[(F_/4)*H_*4];  // [f4][j][ks] : Wdh[j][4f4+ks]

__global__ void prep_kernel(const float* __restrict__ w_ih,
                            const float* __restrict__ w_hh,
                            const float* __restrict__ Wdh) {
    int idx = blockIdx.x * blockDim.x + threadIdx.x;
    int stride = gridDim.x * blockDim.x;
    const int total1 = (K_/4)*G_*4;
    for (int i = idx; i < total1; i += stride) {
        int ks = i & 3;
        int c  = (i >> 2) % G_;
        int k4 = i / (4*G_);
        int k  = 4*k4 + ks;
        float v = (k < IN_) ? w_ih[c*IN_ + k] : w_hh[c*H_ + (k - IN_)];
        g_Wt4[i] = v;
    }
    const int total2 = (F_/4)*H_*4;
    for (int i = idx; i < total2; i += stride) {
        int ks = i & 3;
        int j  = (i >> 2) % H_;
        int f4 = i / (4*H_);
        g_Wdh4[i] = Wdh[j*F_ + 4*f4 + ks];
    }
}

// ---------- f32x2 packed helpers ----------
__device__ __forceinline__ u64 pack2(float a, float b) {
    u64 r; asm("mov.b64 %0,{%1,%2};" : "=l"(r) : "f"(a), "f"(b)); return r;
}
__device__ __forceinline__ void unpack2(u64 v, float& a, float& b) {
    asm("mov.b64 {%0,%1},%2;" : "=f"(a), "=f"(b) : "l"(v));
}
__device__ __forceinline__ u64 fma2(u64 a, u64 b, u64 c) {
    u64 d; asm("fma.rn.f32x2 %0,%1,%2,%3;" : "=l"(d) : "l"(a), "l"(b), "l"(c)); return d;
}
__device__ __forceinline__ float sigmoidf_(float x) {
    return __fdividef(1.f, 1.f + __expf(-x));
}
__device__ __forceinline__ float tanhf_(float x) {
    // tanh(x) = 1 - 2/(exp(2x)+1); __expf keeps rel err ~1e-7 (tanh.approx too coarse)
    return 1.f - __fdividef(2.f, __expf(2.f * x) + 1.f);
}

// GEMM sub-loop over [K4S, K4E), accumulating col group 2 into acc3.
template<int K4S, int K4E>
__device__ __forceinline__ void gemm_part(int j, const float* ush,
                                          u64* ar, u64* az, u64* acc3) {
    const float4* Wp = reinterpret_cast<const float4*>(g_Wt4);
    #pragma unroll 2
    for (int k4 = K4S; k4 < K4E; k4++) {
        const float4* wb = Wp + k4 * G_;
        float4 w0 = wb[j];
        float4 w1 = wb[j + H_];
        float4 w2 = wb[j + 2*H_];
        #pragma unroll
        for (int ks = 0; ks < 4; ks++) {
            int k = 4*k4 + ks;
            float f0 = (&w0.x)[ks], f1 = (&w1.x)[ks], f2 = (&w2.x)[ks];
            u64 wr = pack2(f0, f0);
            u64 wz = pack2(f1, f1);
            u64 wn = pack2(f2, f2);
            const float* ub = ush + k * UPITCH;
            #pragma unroll
            for (int p = 0; p < 8; p++) {
                u64 u = *reinterpret_cast<const u64*>(ub + 2*p);
                ar[p]   = fma2(u, wr, ar[p]);
                az[p]   = fma2(u, wz, az[p]);
                acc3[p] = fma2(u, wn, acc3[p]);
            }
        }
    }
}

__global__ void __launch_bounds__(NT) grud_kernel(
    const float* __restrict__ values, const float* __restrict__ masks,
    const float* __restrict__ deltas, const float* __restrict__ xlocf,
    const float* __restrict__ emp_mean, const float* __restrict__ bdh,
    const float* __restrict__ Wdx, const float* __restrict__ bdx,
    const float* __restrict__ b_ih, const float* __restrict__ b_hh,
    const float* __restrict__ Wc, const float* __restrict__ bc,
    float* __restrict__ out)
{
    // u layout per k-row: 8 row-pairs (p=0..7), pair p = rows (2p, 2p+1)
    // k: [0,64) x_rep | [64,192) h | [192,256) m | [256,384) h (copy)
    __shared__ float ush[K_ * UPITCH];   // 27648 B
    __shared__ float dsh[F_ * UPITCH];   //  4608 B
    __shared__ float s_emp[F_], s_wdx[F_], s_bdx[F_];
    __shared__ float s_red[4][BR];

    const int tid = threadIdx.x;
    const int j   = tid;                  // hidden/gate column owned by this thread
    const int r0  = blockIdx.x * BR;

    if (tid < F_) {
        s_emp[tid] = emp_mean[tid];
        s_wdx[tid] = Wdx[tid * F_ + tid]; // diag(Wdx)
        s_bdx[tid] = bdx[tid];
    }
    for (int i = tid; i < K_*UPITCH; i += NT) ush[i] = 0.f;   // h0 = 0

    const float bdh_j = bdh[j];
    const float br_   = b_ih[j]        + b_hh[j];
    const float bz_   = b_ih[H_ + j]   + b_hh[H_ + j];
    const float bin_  = b_ih[2*H_ + j];
    const float bhn_  = b_hh[2*H_ + j];
    const float wc_j  = Wc[j];

    // staging mapping: thread -> (row sr, 8 features starting at sf)
    const int sr = tid >> 3;
    const int sf = (tid & 7) * 8;
    const int wslot = 2*(sr >> 1) + (sr & 1);   // float slot within a k-row
    const size_t rowbase = (size_t)(r0 + sr) * T_ * F_;

    __syncthreads();

    u64 hd[8];   // decayed h pairs (persist gamma stage -> epilogue)

    for (int t = 0; t < T_; t++) {
        // ---- A: stage inputs, compute x_rep ----
        {
            const float* pv = values + rowbase + (size_t)t*F_ + sf;
            const float* pm = masks  + rowbase + (size_t)t*F_ + sf;
            const float* pd = deltas + rowbase + (size_t)t*F_ + sf;
            const float* pl = xlocf  + rowbase + (size_t)t*F_ + sf;
            float xv[8], xm[8], xd[8], xl[8];
            *reinterpret_cast<float4*>(&xv[0]) = *reinterpret_cast<const float4*>(pv);
            *reinterpret_cast<float4*>(&xv[4]) = *reinterpret_cast<const float4*>(pv+4);
            *reinterpret_cast<float4*>(&xm[0]) = *reinterpret_cast<const float4*>(pm);
            *reinterpret_cast<float4*>(&xm[4]) = *reinterpret_cast<const float4*>(pm+4);
            *reinterpret_cast<float4*>(&xd[0]) = *reinterpret_cast<const float4*>(pd);
            *reinterpret_cast<float4*>(&xd[4]) = *reinterpret_cast<const float4*>(pd+4);
            *reinterpret_cast<float4*>(&xl[0]) = *reinterpret_cast<const float4*>(pl);
            *reinterpret_cast<float4*>(&xl[4]) = *reinterpret_cast<const float4*>(pl+4);
            #pragma unroll
            for (int q = 0; q < 8; q++) {
                int f = sf + q;
                float gx   = __expf(-fmaxf(xd[q]*s_wdx[f] + s_bdx[f], 0.f));
                float xh   = gx*xl[q] + (1.f - gx)*s_emp[f];
                float xrep = xm[q]*xv[q] + (1.f - xm[q])*xh;
                ush[f*UPITCH        + wslot] = xrep;
                ush[(192+f)*UPITCH  + wslot] = xm[q];
                dsh[f*UPITCH        + wslot] = xd[q];
            }
        }
        __syncthreads();   // S1

        // ---- B: gamma_h and h decay (thread j handles column j, all 16 rows) ----
        {
            u64 acc[8];
            #pragma unroll
            for (int p = 0; p < 8; p++) acc[p] = 0ull;
            const float4* Wd = reinterpret_cast<const float4*>(g_Wdh4);
            #pragma unroll 4
            for (int f4 = 0; f4 < F_/4; f4++) {
                float4 w = Wd[f4 * H_ + j];
                #pragma unroll
                for (int ks = 0; ks < 4; ks++) {
                    float wv = (&w.x)[ks];
                    u64 wp = pack2(wv, wv);
                    const float* db = dsh + (4*f4 + ks) * UPITCH;
                    #pragma unroll
                    for (int p = 0; p < 8; p++) {
                        u64 dd = *reinterpret_cast<const u64*>(db + 2*p);
                        acc[p] = fma2(dd, wp, acc[p]);
                    }
                }
            }
            #pragma unroll
            for (int p = 0; p < 8; p++) {
                float a0, a1; unpack2(acc[p], a0, a1);
                float g0 = __expf(-fmaxf(a0 + bdh_j, 0.f));
                float g1 = __expf(-fmaxf(a1 + bdh_j, 0.f));
                float h0, h1;
                unpack2(*reinterpret_cast<u64*>(&ush[(64+j)*UPITCH + 2*p]), h0, h1);
                h0 *= g0; h1 *= g1;
                hd[p] = pack2(h0, h1);
                *reinterpret_cast<u64*>(&ush[(64+j)*UPITCH + 2*p])  = hd[p];
                *reinterpret_cast<u64*>(&ush[(256+j)*UPITCH + 2*p]) = hd[p];
            }
        }
        __syncthreads();   // S2

        // ---- C: gates GEMM  (r, z merged; i_n over k<256, h_n over k>=256) ----
        u64 ar[8], az[8], ai[8], ah[8];
        #pragma unroll
        for (int p = 0; p < 8; p++) { ar[p]=0ull; az[p]=0ull; ai[p]=0ull; ah[p]=0ull; }
        gemm_part<0, 64>(j, ush, ar, az, ai);
        gemm_part<64, 96>(j, ush, ar, az, ah);
        __syncthreads();   // S3

        // ---- D: epilogue -> h_new ----
        #pragma unroll
        for (int p = 0; p < 8; p++) {
            float r0f, r1f, z0f, z1f, i0f, i1f, n0f, n1f, h0f, h1f;
            unpack2(ar[p], r0f, r1f);
            unpack2(az[p], z0f, z1f);
            unpack2(ai[p], i0f, i1f);
            unpack2(ah[p], n0f, n1f);
            unpack2(hd[p], h0f, h1f);
            float rr0 = sigmoidf_(r0f + br_);
            float rr1 = sigmoidf_(r1f + br_);
            float zz0 = sigmoidf_(z0f + bz_);
            float zz1 = sigmoidf_(z1f + bz_);
            float nn0 = tanhf_(i0f + bin_ + rr0 * (n0f + bhn_));
            float nn1 = tanhf_(i1f + bin_ + rr1 * (n1f + bhn_));
            float hn0 = (1.f - zz0)*nn0 + zz0*h0f;
            float hn1 = (1.f - zz1)*nn1 + zz1*h1f;
            *reinterpret_cast<u64*>(&ush[(64+j)*UPITCH + 2*p]) = pack2(hn0, hn1);
        }
        // next-iter S1 makes these h writes visible before anyone reads them
    }

    __syncthreads();

    // ---- final: logits = h @ Wc.T + bc ; sigmoid ----
    float part[BR];
    #pragma unroll
    for (int p = 0; p < 8; p++) {
        float h0, h1;
        unpack2(*reinterpret_cast<u64*>(&ush[(64+j)*UPITCH + 2*p]), h0, h1);
        part[2*p]   = h0 * wc_j;
        part[2*p+1] = h1 * wc_j;
    }
    #pragma unroll
    for (int off = 16; off > 0; off >>= 1) {
        #pragma unroll
        for (int r = 0; r < BR; r++)
            part[r] += __shfl_down_sync(0xffffffffu, part[r], off);
    }
    if ((tid & 31) == 0) {
        int w = tid >> 5;
        #pragma unroll
        for (int r = 0; r < BR; r++) s_red[w][r] = part[r];
    }
    __syncthreads();
    if (tid < BR) {
        float s = s_red[0][tid] + s_red[1][tid] + s_red[2][tid] + s_red[3][tid] + bc[0];
        out[r0 + tid] = sigmoidf_(s);
    }
}

extern "C" void kernel_launch(void* const* d_in, const int* in_sizes, int n_in,
                              void* d_out, int out_size) {
    const float* values   = (const float*)d_in[0];
    const float* masks    = (const float*)d_in[1];
    const float* deltas   = (const float*)d_in[2];
    const float* x_locf   = (const float*)d_in[3];
    const float* emp_mean = (const float*)d_in[4];
    const float* Wdh      = (const float*)d_in[5];
    const float* bdh      = (const float*)d_in[6];
    const float* Wdx      = (const float*)d_in[7];
    const float* bdx      = (const float*)d_in[8];
    const float* w_ih     = (const float*)d_in[9];
    const float* w_hh     = (const float*)d_in[10];
    const float* b_ih     = (const float*)d_in[11];
    const float* b_hh     = (const float*)d_in[12];
    const float* Wc       = (const float*)d_in[13];
    const float* bc       = (const float*)d_in[14];
    float* out = (float*)d_out;

    prep_kernel<<<576, 256>>>(w_ih, w_hh, Wdh);
    grud_kernel<<<NB, NT>>>(values, masks, deltas, x_locf, emp_mean,
                            bdh, Wdx, bdx, b_ih, b_hh, Wc, bc, out);
}

// round 2
// speedup vs baseline: 1.5547x; 1.5547x over previous
#include <cuda_runtime.h>
#include <cstdint>

#define B_   2048
#define T_   200
#define F_   64
#define H_   128
#define IN_  256
#define K_   384   // IN + H
#define G_   384   // 3H
#define BR   16    // batch rows per block
#define NT   512   // 16 warps: 128 cols x 4 k-groups
#define NB   (B_/BR)
#define UPITCH 18  // floats per k-row of u: 8 row-pairs + 1 pad pair
#define RPITCH 25  // u64 pitch per column in reduction buffer (pad for banks)

typedef unsigned long long u64;

// ---------- packed weights (built by prep kernel each launch) ----------
__device__ __align__(16) float g_Wt4[(K_/4)*G_*4];   // [k4][c][ks] : Wfull[c][4k4+ks]
__device__ __align__(16) float g_Wdh4[(F_/4)*H_*4];  // [f4][j][ks] : Wdh[j][4f4+ks]

__global__ void prep_kernel(const float* __restrict__ w_ih,
                            const float* __restrict__ w_hh,
                            const float* __restrict__ Wdh) {
    int idx = blockIdx.x * blockDim.x + threadIdx.x;
    int stride = gridDim.x * blockDim.x;
    const int total1 = (K_/4)*G_*4;
    for (int i = idx; i < total1; i += stride) {
        int ks = i & 3;
        int c  = (i >> 2) % G_;
        int k4 = i / (4*G_);
        int k  = 4*k4 + ks;
        float v = (k < IN_) ? w_ih[c*IN_ + k] : w_hh[c*H_ + (k - IN_)];
        g_Wt4[i] = v;
    }
    const int total2 = (F_/4)*H_*4;
    for (int i = idx; i < total2; i += stride) {
        int ks = i & 3;
        int j  = (i >> 2) % H_;
        int f4 = i / (4*H_);
        g_Wdh4[i] = Wdh[j*F_ + 4*f4 + ks];
    }
}

// ---------- f32x2 packed helpers ----------
__device__ __forceinline__ u64 pack2(float a, float b) {
    u64 r; asm("mov.b64 %0,{%1,%2};" : "=l"(r) : "f"(a), "f"(b)); return r;
}
__device__ __forceinline__ void unpack2(u64 v, float& a, float& b) {
    asm("mov.b64 {%0,%1},%2;" : "=f"(a), "=f"(b) : "l"(v));
}
__device__ __forceinline__ u64 fma2(u64 a, u64 b, u64 c) {
    u64 d; asm("fma.rn.f32x2 %0,%1,%2,%3;" : "=l"(d) : "l"(a), "l"(b), "l"(c)); return d;
}
__device__ __forceinline__ u64 add2(u64 a, u64 b) {
    u64 d; asm("add.rn.f32x2 %0,%1,%2;" : "=l"(d) : "l"(a), "l"(b)); return d;
}
__device__ __forceinline__ float sigmoidf_(float x) {
    return __fdividef(1.f, 1.f + __expf(-x));
}
__device__ __forceinline__ float tanhf_(float x) {
    return 1.f - __fdividef(2.f, __expf(2.f * x) + 1.f);
}

// GEMM sub-loop over k4 in [K4S, K4E): 3 gate columns (j, j+128, j+256),
// 8 row-pairs. Third column group accumulates into acc3.
template<int K4S, int K4E>
__device__ __forceinline__ void gemm_part(int j, const float* ush,
                                          u64* ar, u64* az, u64* acc3) {
    const float4* Wp = reinterpret_cast<const float4*>(g_Wt4);
    #pragma unroll 2
    for (int k4 = K4S; k4 < K4E; k4++) {
        const float4* wb = Wp + k4 * G_;
        float4 w0 = wb[j];
        float4 w1 = wb[j + H_];
        float4 w2 = wb[j + 2*H_];
        #pragma unroll
        for (int ks = 0; ks < 4; ks++) {
            int k = 4*k4 + ks;
            float f0 = (&w0.x)[ks], f1 = (&w1.x)[ks], f2 = (&w2.x)[ks];
            u64 wr = pack2(f0, f0);
            u64 wz = pack2(f1, f1);
            u64 wn = pack2(f2, f2);
            const float* ub = ush + k * UPITCH;
            #pragma unroll
            for (int p = 0; p < 8; p++) {
                u64 u = *reinterpret_cast<const u64*>(ub + 2*p);
                ar[p]   = fma2(u, wr, ar[p]);
                az[p]   = fma2(u, wz, az[p]);
                acc3[p] = fma2(u, wn, acc3[p]);
            }
        }
    }
}

// dynamic smem layout (bytes):
//   ush   : K_*UPITCH floats        = 27648
//   dsh   : F_*UPITCH floats        =  4608
//   red   : 3*128*RPITCH u64        = 76800
//   s_emp/s_wdx/s_bdx : 64 floats each = 768
//   s_redf: 4*BR floats             = 256
#define SMEM_BYTES (K_*UPITCH*4 + F_*UPITCH*4 + 3*128*RPITCH*8 + 3*F_*4 + 4*BR*4)

__global__ void __launch_bounds__(NT, 1) grud_kernel(
    const float* __restrict__ values, const float* __restrict__ masks,
    const float* __restrict__ deltas, const float* __restrict__ xlocf,
    const float* __restrict__ emp_mean, const float* __restrict__ bdh,
    const float* __restrict__ Wdx, const float* __restrict__ bdx,
    const float* __restrict__ b_ih, const float* __restrict__ b_hh,
    const float* __restrict__ Wc, const float* __restrict__ bc,
    float* __restrict__ out)
{
    extern __shared__ char smem_raw[];
    float* ush  = reinterpret_cast<float*>(smem_raw);           // [K_][UPITCH]
    float* dsh  = ush + K_*UPITCH;                              // [F_][UPITCH]
    u64*   red  = reinterpret_cast<u64*>(dsh + F_*UPITCH);      // [3][128][RPITCH]
    float* s_emp  = reinterpret_cast<float*>(red + 3*128*RPITCH);
    float* s_wdx  = s_emp + F_;
    float* s_bdx  = s_wdx + F_;
    float* s_redf = s_bdx + F_;                                  // [4][BR]

    const int tid = threadIdx.x;
    const int j   = tid & 127;   // gate/hidden column
    const int kg  = tid >> 7;    // k-group 0..3
    const int r0  = blockIdx.x * BR;

    if (tid < F_) {
        s_emp[tid] = emp_mean[tid];
        s_wdx[tid] = Wdx[tid * F_ + tid];
        s_bdx[tid] = bdx[tid];
    }
    for (int i = tid; i < K_*UPITCH; i += NT) ush[i] = 0.f;   // h0 = 0

    const float bdh_j = bdh[j];
    const float br_   = b_ih[j]        + b_hh[j];
    const float bz_   = b_ih[H_ + j]   + b_hh[H_ + j];
    const float bin_  = b_ih[2*H_ + j];
    const float bhn_  = b_hh[2*H_ + j];
    const float wc_j  = Wc[j];

    // staging mapping: sr = batch row in block, lane covers 2 features
    const int sr   = tid >> 5;           // 0..15
    const int lane = tid & 31;
    const int sf   = lane * 2;
    const size_t rowbase = (size_t)(r0 + sr) * T_ * F_;

    // decay mapping: thread (j, kg) handles column j, pairs 2kg and 2kg+1
    const int dp = 4 * kg;   // float offset of first owned pair

    __syncthreads();

    for (int t = 0; t < T_; t++) {
        // ---- A: stage inputs, compute x_rep ----
        {
            const size_t base = rowbase + (size_t)t*F_ + sf;
            float2 xv = *reinterpret_cast<const float2*>(values + base);
            float2 xm = *reinterpret_cast<const float2*>(masks  + base);
            float2 xd = *reinterpret_cast<const float2*>(deltas + base);
            float2 xl = *reinterpret_cast<const float2*>(xlocf  + base);
            float v_[2] = {xv.x, xv.y}, m_[2] = {xm.x, xm.y};
            float d_[2] = {xd.x, xd.y}, l_[2] = {xl.x, xl.y};
            #pragma unroll
            for (int q = 0; q < 2; q++) {
                int f = sf + q;
                float gx   = __expf(-fmaxf(d_[q]*s_wdx[f] + s_bdx[f], 0.f));
                float xh   = gx*l_[q] + (1.f - gx)*s_emp[f];
                float xrep = m_[q]*v_[q] + (1.f - m_[q])*xh;
                ush[f*UPITCH        + sr] = xrep;
                ush[(192+f)*UPITCH  + sr] = m_[q];
                dsh[f*UPITCH        + sr] = d_[q];
            }
        }
        __syncthreads();   // S1

        // ---- B: gamma_h + h decay (thread (j,kg): col j, 2 pairs) ----
        {
            u64 acc0 = 0ull, acc1 = 0ull;
            const float4* Wd = reinterpret_cast<const float4*>(g_Wdh4);
            #pragma unroll 4
            for (int f4 = 0; f4 < F_/4; f4++) {
                float4 w = Wd[f4 * H_ + j];
                #pragma unroll
                for (int ks = 0; ks < 4; ks++) {
                    float wv = (&w.x)[ks];
                    u64 wp = pack2(wv, wv);
                    const float* db = dsh + (4*f4 + ks) * UPITCH;
                    acc0 = fma2(*reinterpret_cast<const u64*>(db + dp),     wp, acc0);
                    acc1 = fma2(*reinterpret_cast<const u64*>(db + dp + 2), wp, acc1);
                }
            }
            float a0, a1, b0, b1;
            unpack2(acc0, a0, a1);
            unpack2(acc1, b0, b1);
            float g00 = __expf(-fmaxf(a0 + bdh_j, 0.f));
            float g01 = __expf(-fmaxf(a1 + bdh_j, 0.f));
            float g10 = __expf(-fmaxf(b0 + bdh_j, 0.f));
            float g11 = __expf(-fmaxf(b1 + bdh_j, 0.f));
            float* hrow = ush + (64 + j) * UPITCH;
            float h00, h01, h10, h11;
            unpack2(*reinterpret_cast<u64*>(hrow + dp),     h00, h01);
            unpack2(*reinterpret_cast<u64*>(hrow + dp + 2), h10, h11);
            u64 hd0 = pack2(h00*g00, h01*g01);
            u64 hd1 = pack2(h10*g10, h11*g11);
            *reinterpret_cast<u64*>(hrow + dp)     = hd0;
            *reinterpret_cast<u64*>(hrow + dp + 2) = hd1;
            float* hcpy = ush + (256 + j) * UPITCH;
            *reinterpret_cast<u64*>(hcpy + dp)     = hd0;
            *reinterpret_cast<u64*>(hcpy + dp + 2) = hd1;
        }
        __syncthreads();   // S2

        // ---- C: gates GEMM, 4-way k-split ----
        // kg0: k[0,128)   -> r,z,i      kg1: k[128,256) -> r,z,i
        // kg2: k[256,320) -> r,z,h      kg3: k[320,384) -> r,z,h
        u64 ar[8], az[8], a3[8];
        #pragma unroll
        for (int p = 0; p < 8; p++) { ar[p]=0ull; az[p]=0ull; a3[p]=0ull; }
        if      (kg == 0) gemm_part< 0, 32>(j, ush, ar, az, a3);
        else if (kg == 1) gemm_part<32, 64>(j, ush, ar, az, a3);
        else if (kg == 2) gemm_part<64, 80>(j, ush, ar, az, a3);
        else              gemm_part<80, 96>(j, ush, ar, az, a3);

        // ---- partials to smem (kg >= 1) ----
        if (kg >= 1) {
            u64* dst = red + ((size_t)(kg-1)*128 + j) * RPITCH;
            #pragma unroll
            for (int p = 0; p < 8; p++) {
                dst[p]      = ar[p];
                dst[8 + p]  = az[p];
                dst[16 + p] = a3[p];
            }
        }
        __syncthreads();   // S3

        // ---- D: reduce + epilogue (kg == 0) ----
        if (kg == 0) {
            u64 ah[8];
            #pragma unroll
            for (int p = 0; p < 8; p++) ah[p] = 0ull;
            #pragma unroll
            for (int g = 1; g <= 3; g++) {
                const u64* s = red + ((size_t)(g-1)*128 + j) * RPITCH;
                #pragma unroll
                for (int p = 0; p < 8; p++) {
                    ar[p] = add2(ar[p], s[p]);
                    az[p] = add2(az[p], s[8 + p]);
                    if (g == 1) a3[p] = add2(a3[p], s[16 + p]);
                    else        ah[p] = add2(ah[p], s[16 + p]);
                }
            }
            float* hrow = ush + (64 + j) * UPITCH;
            #pragma unroll
            for (int p = 0; p < 8; p++) {
                float r0f, r1f, z0f, z1f, i0f, i1f, n0f, n1f, h0f, h1f;
                unpack2(ar[p], r0f, r1f);
                unpack2(az[p], z0f, z1f);
                unpack2(a3[p], i0f, i1f);
                unpack2(ah[p], n0f, n1f);
                unpack2(*reinterpret_cast<u64*>(hrow + 2*p), h0f, h1f);
                float rr0 = sigmoidf_(r0f + br_);
                float rr1 = sigmoidf_(r1f + br_);
                float zz0 = sigmoidf_(z0f + bz_);
                float zz1 = sigmoidf_(z1f + bz_);
                float nn0 = tanhf_(i0f + bin_ + rr0 * (n0f + bhn_));
                float nn1 = tanhf_(i1f + bin_ + rr1 * (n1f + bhn_));
                float hn0 = (1.f - zz0)*nn0 + zz0*h0f;
                float hn1 = (1.f - zz1)*nn1 + zz1*h1f;
                *reinterpret_cast<u64*>(hrow + 2*p) = pack2(hn0, hn1);
            }
        }
        // next-iter S1 publishes h writes before B reads them
    }

    __syncthreads();

    // ---- final: logits = h @ Wc.T + bc ; sigmoid (first 128 threads) ----
    if (tid < 128) {
        float part[BR];
        #pragma unroll
        for (int p = 0; p < 8; p++) {
            float h0, h1;
            unpack2(*reinterpret_cast<u64*>(&ush[(64+j)*UPITCH + 2*p]), h0, h1);
            part[2*p]   = h0 * wc_j;
            part[2*p+1] = h1 * wc_j;
        }
        #pragma unroll
        for (int off = 16; off > 0; off >>= 1) {
            #pragma unroll
            for (int r = 0; r < BR; r++)
                part[r] += __shfl_down_sync(0xffffffffu, part[r], off);
        }
        if ((tid & 31) == 0) {
            int w = tid >> 5;
            #pragma unroll
            for (int r = 0; r < BR; r++) s_redf[w*BR + r] = part[r];
        }
    }
    __syncthreads();
    if (tid < BR) {
        float s = s_redf[0*BR + tid] + s_redf[1*BR + tid]
                + s_redf[2*BR + tid] + s_redf[3*BR + tid] + bc[0];
        out[r0 + tid] = sigmoidf_(s);
    }
}

extern "C" void kernel_launch(void* const* d_in, const int* in_sizes, int n_in,
                              void* d_out, int out_size) {
    const float* values   = (const float*)d_in[0];
    const float* masks    = (const float*)d_in[1];
    const float* deltas   = (const float*)d_in[2];
    const float* x_locf   = (const float*)d_in[3];
    const float* emp_mean = (const float*)d_in[4];
    const float* Wdh      = (const float*)d_in[5];
    const float* bdh      = (const float*)d_in[6];
    const float* Wdx      = (const float*)d_in[7];
    const float* bdx      = (const float*)d_in[8];
    const float* w_ih     = (const float*)d_in[9];
    const float* w_hh     = (const float*)d_in[10];
    const float* b_ih     = (const float*)d_in[11];
    const float* b_hh     = (const float*)d_in[12];
    const float* Wc       = (const float*)d_in[13];
    const float* bc       = (const float*)d_in[14];
    float* out = (float*)d_out;

    cudaFuncSetAttribute(grud_kernel,
                         cudaFuncAttributeMaxDynamicSharedMemorySize, SMEM_BYTES);

    prep_kernel<<<576, 256>>>(w_ih, w_hh, Wdh);
    grud_kernel<<<NB, NT, SMEM_BYTES>>>(values, masks, deltas, x_locf, emp_mean,
                                        bdh, Wdx, bdx, b_ih, b_hh, Wc, bc, out);
}

// round 3
// speedup vs baseline: 1.6375x; 1.0533x over previous
#include <cuda_runtime.h>
#include <cstdint>

#define B_   2048
#define T_   200
#define F_   64
#define H_   128
#define IN_  256
#define K_   384   // IN + H
#define G_   384   // 3H
#define BR   16    // batch rows per block
#define NT   512   // 16 warps: 128 cols x 4 k-groups
#define NB   (B_/BR)
#define UPITCH 20  // floats per k-row of u: 8 row-pairs (16 floats) + pad, 16B aligned
#define RPITCH 33  // u64 pitch per (group, column) slot in reduction buffer

typedef unsigned long long u64;

// ---------- packed weights (built by prep kernel each launch) ----------
__device__ __align__(16) float g_Wt4[(K_/4)*G_*4];   // [k4][c][ks] : Wfull[c][4k4+ks]
__device__ __align__(16) float g_Wdh4[(F_/4)*H_*4];  // [f4][j][ks] : Wdh[j][4f4+ks]

__global__ void prep_kernel(const float* __restrict__ w_ih,
                            const float* __restrict__ w_hh,
                            const float* __restrict__ Wdh) {
    int idx = blockIdx.x * blockDim.x + threadIdx.x;
    int stride = gridDim.x * blockDim.x;
    const int total1 = (K_/4)*G_*4;
    for (int i = idx; i < total1; i += stride) {
        int ks = i & 3;
        int c  = (i >> 2) % G_;
        int k4 = i / (4*G_);
        int k  = 4*k4 + ks;
        float v = (k < IN_) ? w_ih[c*IN_ + k] : w_hh[c*H_ + (k - IN_)];
        g_Wt4[i] = v;
    }
    const int total2 = (F_/4)*H_*4;
    for (int i = idx; i < total2; i += stride) {
        int ks = i & 3;
        int j  = (i >> 2) % H_;
        int f4 = i / (4*H_);
        g_Wdh4[i] = Wdh[j*F_ + 4*f4 + ks];
    }
}

// ---------- f32x2 packed helpers ----------
__device__ __forceinline__ u64 pack2(float a, float b) {
    u64 r; asm("mov.b64 %0,{%1,%2};" : "=l"(r) : "f"(a), "f"(b)); return r;
}
__device__ __forceinline__ void unpack2(u64 v, float& a, float& b) {
    asm("mov.b64 {%0,%1},%2;" : "=f"(a), "=f"(b) : "l"(v));
}
__device__ __forceinline__ u64 fma2(u64 a, u64 b, u64 c) {
    u64 d; asm("fma.rn.f32x2 %0,%1,%2,%3;" : "=l"(d) : "l"(a), "l"(b), "l"(c)); return d;
}
__device__ __forceinline__ u64 add2(u64 a, u64 b) {
    u64 d; asm("add.rn.f32x2 %0,%1,%2;" : "=l"(d) : "l"(a), "l"(b)); return d;
}
__device__ __forceinline__ float sigmoidf_(float x) {
    return __fdividef(1.f, 1.f + __expf(-x));
}
__device__ __forceinline__ float tanhf_(float x) {
    return 1.f - __fdividef(2.f, __expf(2.f * x) + 1.f);
}

// GEMM sub-loop over k4 in [K4S, K4E): 3 gate columns (j, j+128, j+256),
// 8 row-pairs loaded via LDS.128 (ulonglong2). Accumulates into ar/az/a3.
template<int K4S, int K4E>
__device__ __forceinline__ void gemm_part(int j, const float* ush,
                                          u64* ar, u64* az, u64* a3) {
    const float4* Wp = reinterpret_cast<const float4*>(g_Wt4);
    #pragma unroll 2
    for (int k4 = K4S; k4 < K4E; k4++) {
        const float4* wb = Wp + k4 * G_;
        float4 w0 = wb[j];
        float4 w1 = wb[j + H_];
        float4 w2 = wb[j + 2*H_];
        #pragma unroll
        for (int ks = 0; ks < 4; ks++) {
            float f0 = (&w0.x)[ks], f1 = (&w1.x)[ks], f2 = (&w2.x)[ks];
            u64 wr = pack2(f0, f0);
            u64 wz = pack2(f1, f1);
            u64 wn = pack2(f2, f2);
            const ulonglong2* ub =
                reinterpret_cast<const ulonglong2*>(ush + (4*k4 + ks) * UPITCH);
            #pragma unroll
            for (int q = 0; q < 4; q++) {
                ulonglong2 u2 = ub[q];
                ar[2*q]   = fma2(u2.x, wr, ar[2*q]);
                az[2*q]   = fma2(u2.x, wz, az[2*q]);
                a3[2*q]   = fma2(u2.x, wn, a3[2*q]);
                ar[2*q+1] = fma2(u2.y, wr, ar[2*q+1]);
                az[2*q+1] = fma2(u2.y, wz, az[2*q+1]);
                a3[2*q+1] = fma2(u2.y, wn, a3[2*q+1]);
            }
        }
    }
}

// dynamic smem layout:
//   ush : K_*UPITCH floats   = 30720 B
//   dsh : F_*UPITCH floats   =  5120 B
//   red : 4*128*RPITCH u64   = 135168 B
//   s_emp/s_wdx/s_bdx        =    768 B
//   s_redf                   =    256 B
#define SMEM_BYTES (K_*UPITCH*4 + F_*UPITCH*4 + 4*128*RPITCH*8 + 3*F_*4 + 4*BR*4)

__global__ void __launch_bounds__(NT, 1) grud_kernel(
    const float* __restrict__ values, const float* __restrict__ masks,
    const float* __restrict__ deltas, const float* __restrict__ xlocf,
    const float* __restrict__ emp_mean, const float* __restrict__ bdh,
    const float* __restrict__ Wdx, const float* __restrict__ bdx,
    const float* __restrict__ b_ih, const float* __restrict__ b_hh,
    const float* __restrict__ Wc, const float* __restrict__ bc,
    float* __restrict__ out)
{
    extern __shared__ char smem_raw[];
    float* ush  = reinterpret_cast<float*>(smem_raw);           // [K_][UPITCH]
    float* dsh  = ush + K_*UPITCH;                              // [F_][UPITCH]
    u64*   red  = reinterpret_cast<u64*>(dsh + F_*UPITCH);      // [4][128][RPITCH]
    float* s_emp  = reinterpret_cast<float*>(red + 4*128*RPITCH);
    float* s_wdx  = s_emp + F_;
    float* s_bdx  = s_wdx + F_;
    float* s_redf = s_bdx + F_;                                  // [4][BR]

    const int tid = threadIdx.x;
    const int j   = tid & 127;   // gate/hidden column
    const int kg  = tid >> 7;    // k-group 0..3
    const int r0  = blockIdx.x * BR;

    if (tid < F_) {
        s_emp[tid] = emp_mean[tid];
        s_wdx[tid] = Wdx[tid * F_ + tid];
        s_bdx[tid] = bdx[tid];
    }
    for (int i = tid; i < K_*UPITCH; i += NT) ush[i] = 0.f;   // h0 = 0

    const float bdh_j = bdh[j];
    const float br_   = b_ih[j]        + b_hh[j];
    const float bz_   = b_ih[H_ + j]   + b_hh[H_ + j];
    const float bin_  = b_ih[2*H_ + j];
    const float bhn_  = b_hh[2*H_ + j];
    const float wc_j  = Wc[j];

    // staging mapping: sr = batch row in block, lane covers 2 features
    const int sr   = tid >> 5;           // 0..15
    const int lane = tid & 31;
    const int sf   = lane * 2;
    const size_t rowbase = (size_t)(r0 + sr) * T_ * F_;

    // decay/epilogue mapping: thread (j, kg) owns column j, row-pairs 2kg, 2kg+1
    const int dp = 4 * kg;   // float offset of first owned pair

    u64* myslot = red + (size_t)(kg*128 + j) * RPITCH;

    __syncthreads();

    for (int t = 0; t < T_; t++) {
        // ---- A: stage inputs, compute x_rep ----
        {
            const size_t base = rowbase + (size_t)t*F_ + sf;
            float2 xv = *reinterpret_cast<const float2*>(values + base);
            float2 xm = *reinterpret_cast<const float2*>(masks  + base);
            float2 xd = *reinterpret_cast<const float2*>(deltas + base);
            float2 xl = *reinterpret_cast<const float2*>(xlocf  + base);
            float v_[2] = {xv.x, xv.y}, m_[2] = {xm.x, xm.y};
            float d_[2] = {xd.x, xd.y}, l_[2] = {xl.x, xl.y};
            #pragma unroll
            for (int q = 0; q < 2; q++) {
                int f = sf + q;
                float gx   = __expf(-fmaxf(d_[q]*s_wdx[f] + s_bdx[f], 0.f));
                float xh   = gx*l_[q] + (1.f - gx)*s_emp[f];
                float xrep = m_[q]*v_[q] + (1.f - m_[q])*xh;
                ush[f*UPITCH        + sr] = xrep;
                ush[(192+f)*UPITCH  + sr] = m_[q];
                dsh[f*UPITCH        + sr] = d_[q];
            }
        }
        __syncthreads();   // S1

        // ---- B: gamma_h + h decay (thread (j,kg): col j, pairs 2kg,2kg+1) ----
        {
            u64 acc0 = 0ull, acc1 = 0ull;
            const float4* Wd = reinterpret_cast<const float4*>(g_Wdh4);
            #pragma unroll 4
            for (int f4 = 0; f4 < F_/4; f4++) {
                float4 w = Wd[f4 * H_ + j];
                #pragma unroll
                for (int ks = 0; ks < 4; ks++) {
                    float wv = (&w.x)[ks];
                    u64 wp = pack2(wv, wv);
                    ulonglong2 dd = *reinterpret_cast<const ulonglong2*>(
                        dsh + (4*f4 + ks) * UPITCH + dp);
                    acc0 = fma2(dd.x, wp, acc0);
                    acc1 = fma2(dd.y, wp, acc1);
                }
            }
            float a0, a1, b0, b1;
            unpack2(acc0, a0, a1);
            unpack2(acc1, b0, b1);
            float g00 = __expf(-fmaxf(a0 + bdh_j, 0.f));
            float g01 = __expf(-fmaxf(a1 + bdh_j, 0.f));
            float g10 = __expf(-fmaxf(b0 + bdh_j, 0.f));
            float g11 = __expf(-fmaxf(b1 + bdh_j, 0.f));
            float* hrow = ush + (64 + j) * UPITCH;
            float h00, h01, h10, h11;
            unpack2(*reinterpret_cast<u64*>(hrow + dp),     h00, h01);
            unpack2(*reinterpret_cast<u64*>(hrow + dp + 2), h10, h11);
            u64 hd0 = pack2(h00*g00, h01*g01);
            u64 hd1 = pack2(h10*g10, h11*g11);
            *reinterpret_cast<u64*>(hrow + dp)     = hd0;
            *reinterpret_cast<u64*>(hrow + dp + 2) = hd1;
            float* hcpy = ush + (256 + j) * UPITCH;
            *reinterpret_cast<u64*>(hcpy + dp)     = hd0;
            *reinterpret_cast<u64*>(hcpy + dp + 2) = hd1;
        }
        __syncthreads();   // S2

        // ---- C: gates GEMM, balanced 4-way k-split (24 k4 each) ----
        // kg0: k4[0,24)  (r,z,i)     kg1: k4[24,48) (r,z,i)
        // kg2: k4[48,64) (r,z,i) + k4[64,72) (r,z,h)
        // kg3: k4[72,96) (r,z,h)
        {
            u64 ar[8], az[8], a3[8];
            #pragma unroll
            for (int p = 0; p < 8; p++) { ar[p]=0ull; az[p]=0ull; a3[p]=0ull; }
            if (kg == 0) {
                gemm_part< 0, 24>(j, ush, ar, az, a3);
            } else if (kg == 1) {
                gemm_part<24, 48>(j, ush, ar, az, a3);
            } else if (kg == 2) {
                gemm_part<48, 64>(j, ush, ar, az, a3);
                #pragma unroll
                for (int p = 0; p < 8; p++) { myslot[16 + p] = a3[p]; a3[p] = 0ull; }
                gemm_part<64, 72>(j, ush, ar, az, a3);
                #pragma unroll
                for (int p = 0; p < 8; p++) {
                    myslot[p] = ar[p]; myslot[8 + p] = az[p]; myslot[24 + p] = a3[p];
                }
            } else {
                gemm_part<72, 96>(j, ush, ar, az, a3);
            }
            if (kg != 2) {
                #pragma unroll
                for (int p = 0; p < 8; p++) {
                    myslot[p] = ar[p]; myslot[8 + p] = az[p]; myslot[16 + p] = a3[p];
                }
            }
        }
        __syncthreads();   // S3

        // ---- D: reduce + epilogue, distributed: thread (j,kg) -> pairs 2kg,2kg+1 ----
        {
            const u64* g0 = red + (size_t)(0*128 + j) * RPITCH;
            const u64* g1 = red + (size_t)(1*128 + j) * RPITCH;
            const u64* g2 = red + (size_t)(2*128 + j) * RPITCH;
            const u64* g3 = red + (size_t)(3*128 + j) * RPITCH;
            float* hrow = ush + (64 + j) * UPITCH;
            #pragma unroll
            for (int pi = 0; pi < 2; pi++) {
                int p = 2*kg + pi;
                u64 rv = add2(add2(g0[p],      g1[p]),      add2(g2[p],      g3[p]));
                u64 zv = add2(add2(g0[8 + p],  g1[8 + p]),  add2(g2[8 + p],  g3[8 + p]));
                u64 iv = add2(add2(g0[16 + p], g1[16 + p]), g2[16 + p]);
                u64 hv = add2(g2[24 + p], g3[16 + p]);
                float r0f, r1f, z0f, z1f, i0f, i1f, n0f, n1f, h0f, h1f;
                unpack2(rv, r0f, r1f);
                unpack2(zv, z0f, z1f);
                unpack2(iv, i0f, i1f);
                unpack2(hv, n0f, n1f);
                unpack2(*reinterpret_cast<u64*>(hrow + 2*p), h0f, h1f);
                float rr0 = sigmoidf_(r0f + br_);
                float rr1 = sigmoidf_(r1f + br_);
                float zz0 = sigmoidf_(z0f + bz_);
                float zz1 = sigmoidf_(z1f + bz_);
                float nn0 = tanhf_(i0f + bin_ + rr0 * (n0f + bhn_));
                float nn1 = tanhf_(i1f + bin_ + rr1 * (n1f + bhn_));
                float hn0 = (1.f - zz0)*nn0 + zz0*h0f;
                float hn1 = (1.f - zz1)*nn1 + zz1*h1f;
                *reinterpret_cast<u64*>(hrow + 2*p) = pack2(hn0, hn1);
            }
        }
        // next-iter S1 publishes h writes before stage C readers; stage B of
        // thread (j,kg) re-reads only its own pairs (same thread) — safe.
    }

    __syncthreads();

    // ---- final: logits = h @ Wc.T + bc ; sigmoid (first 128 threads) ----
    if (tid < 128) {
        float part[BR];
        #pragma unroll
        for (int p = 0; p < 8; p++) {
            float h0, h1;
            unpack2(*reinterpret_cast<u64*>(&ush[(64+j)*UPITCH + 2*p]), h0, h1);
            part[2*p]   = h0 * wc_j;
            part[2*p+1] = h1 * wc_j;
        }
        #pragma unroll
        for (int off = 16; off > 0; off >>= 1) {
            #pragma unroll
            for (int r = 0; r < BR; r++)
                part[r] += __shfl_down_sync(0xffffffffu, part[r], off);
        }
        if ((tid & 31) == 0) {
            int w = tid >> 5;
            #pragma unroll
            for (int r = 0; r < BR; r++) s_redf[w*BR + r] = part[r];
        }
    }
    __syncthreads();
    if (tid < BR) {
        float s = s_redf[0*BR + tid] + s_redf[1*BR + tid]
                + s_redf[2*BR + tid] + s_redf[3*BR + tid] + bc[0];
        out[r0 + tid] = sigmoidf_(s);
    }
}

extern "C" void kernel_launch(void* const* d_in, const int* in_sizes, int n_in,
                              void* d_out, int out_size) {
    const float* values   = (const float*)d_in[0];
    const float* masks    = (const float*)d_in[1];
    const float* deltas   = (const float*)d_in[2];
    const float* x_locf   = (const float*)d_in[3];
    const float* emp_mean = (const float*)d_in[4];
    const float* Wdh      = (const float*)d_in[5];
    const float* bdh      = (const float*)d_in[6];
    const float* Wdx      = (const float*)d_in[7];
    const float* bdx      = (const float*)d_in[8];
    const float* w_ih     = (const float*)d_in[9];
    const float* w_hh     = (const float*)d_in[10];
    const float* b_ih     = (const float*)d_in[11];
    const float* b_hh     = (const float*)d_in[12];
    const float* Wc       = (const float*)d_in[13];
    const float* bc       = (const float*)d_in[14];
    float* out = (float*)d_out;

    cudaFuncSetAttribute(grud_kernel,
                         cudaFuncAttributeMaxDynamicSharedMemorySize, SMEM_BYTES);

    prep_kernel<<<576, 256>>>(w_ih, w_hh, Wdh);
    grud_kernel<<<NB, NT, SMEM_BYTES>>>(values, masks, deltas, x_locf, emp_mean,
                                        bdh, Wdx, bdx, b_ih, b_hh, Wc, bc, out);
}

// round 4
// speedup vs baseline: 1.6598x; 1.0136x over previous
#include <cuda_runtime.h>
#include <cstdint>

#define B_   2048
#define T_   200
#define F_   64
#define H_   128
#define IN_  256
#define K_   384   // IN + H
#define G_   384   // 3H
#define BR   14    // batch rows per block
#define NP   7     // row pairs per block
#define NT   768   // 24 warps: 128 cols x 6 k-groups
#define NB   147   // 147*14 = 2058 >= 2048 (last block: 4 valid rows)
#define UPITCH 20  // floats per k-row of u (8 pair slots + pad; pair 7 unused)
#define RPITCH 25  // u64 per (group, column) slot: 7 r + 7 z + 7 third + pad

typedef unsigned long long u64;

// ---------- packed weights (built by prep kernel each launch) ----------
__device__ __align__(16) float g_Wt4[(K_/4)*G_*4];   // [k4][c][ks] : Wfull[c][4k4+ks]
__device__ __align__(16) float g_Wdh4[(F_/4)*H_*4];  // [f4][j][ks] : Wdh[j][4f4+ks]

__global__ void prep_kernel(const float* __restrict__ w_ih,
                            const float* __restrict__ w_hh,
                            const float* __restrict__ Wdh) {
    int idx = blockIdx.x * blockDim.x + threadIdx.x;
    int stride = gridDim.x * blockDim.x;
    const int total1 = (K_/4)*G_*4;
    for (int i = idx; i < total1; i += stride) {
        int ks = i & 3;
        int c  = (i >> 2) % G_;
        int k4 = i / (4*G_);
        int k  = 4*k4 + ks;
        float v = (k < IN_) ? w_ih[c*IN_ + k] : w_hh[c*H_ + (k - IN_)];
        g_Wt4[i] = v;
    }
    const int total2 = (F_/4)*H_*4;
    for (int i = idx; i < total2; i += stride) {
        int ks = i & 3;
        int j  = (i >> 2) % H_;
        int f4 = i / (4*H_);
        g_Wdh4[i] = Wdh[j*F_ + 4*f4 + ks];
    }
}

// ---------- f32x2 packed helpers ----------
__device__ __forceinline__ u64 pack2(float a, float b) {
    u64 r; asm("mov.b64 %0,{%1,%2};" : "=l"(r) : "f"(a), "f"(b)); return r;
}
__device__ __forceinline__ void unpack2(u64 v, float& a, float& b) {
    asm("mov.b64 {%0,%1},%2;" : "=f"(a), "=f"(b) : "l"(v));
}
__device__ __forceinline__ u64 fma2(u64 a, u64 b, u64 c) {
    u64 d; asm("fma.rn.f32x2 %0,%1,%2,%3;" : "=l"(d) : "l"(a), "l"(b), "l"(c)); return d;
}
__device__ __forceinline__ u64 add2(u64 a, u64 b) {
    u64 d; asm("add.rn.f32x2 %0,%1,%2;" : "=l"(d) : "l"(a), "l"(b)); return d;
}
__device__ __forceinline__ float sigmoidf_(float x) {
    return __fdividef(1.f, 1.f + __expf(-x));
}
__device__ __forceinline__ float tanhf_(float x) {
    return 1.f - __fdividef(2.f, __expf(2.f * x) + 1.f);
}

// GEMM sub-loop: 3 gate columns (j, j+128, j+256), 7 row-pairs.
// Loads per ks: 3x LDS.128 + 1x LDS.64 (pairs 0..6).
template<int K4S, int K4E>
__device__ __forceinline__ void gemm_part(int j, const float* ush,
                                          u64* ar, u64* az, u64* a3) {
    const float4* Wp = reinterpret_cast<const float4*>(g_Wt4);
    #pragma unroll 1
    for (int k4 = K4S; k4 < K4E; k4++) {
        float4 w0 = Wp[k4 * G_ + j];
        float4 w1 = Wp[k4 * G_ + j + H_];
        float4 w2 = Wp[k4 * G_ + j + 2*H_];
        #pragma unroll
        for (int ks = 0; ks < 4; ks++) {
            float f0 = (&w0.x)[ks], f1 = (&w1.x)[ks], f2 = (&w2.x)[ks];
            u64 wr = pack2(f0, f0);
            u64 wz = pack2(f1, f1);
            u64 wn = pack2(f2, f2);
            const float* ub = ush + (4*k4 + ks) * UPITCH;
            ulonglong2 u01 = *reinterpret_cast<const ulonglong2*>(ub);
            ulonglong2 u23 = *reinterpret_cast<const ulonglong2*>(ub + 4);
            ulonglong2 u45 = *reinterpret_cast<const ulonglong2*>(ub + 8);
            u64        u6  = *reinterpret_cast<const u64*>(ub + 12);
            ar[0] = fma2(u01.x, wr, ar[0]);
            az[0] = fma2(u01.x, wz, az[0]);
            a3[0] = fma2(u01.x, wn, a3[0]);
            ar[1] = fma2(u01.y, wr, ar[1]);
            az[1] = fma2(u01.y, wz, az[1]);
            a3[1] = fma2(u01.y, wn, a3[1]);
            ar[2] = fma2(u23.x, wr, ar[2]);
            az[2] = fma2(u23.x, wz, az[2]);
            a3[2] = fma2(u23.x, wn, a3[2]);
            ar[3] = fma2(u23.y, wr, ar[3]);
            az[3] = fma2(u23.y, wz, az[3]);
            a3[3] = fma2(u23.y, wn, a3[3]);
            ar[4] = fma2(u45.x, wr, ar[4]);
            az[4] = fma2(u45.x, wz, az[4]);
            a3[4] = fma2(u45.x, wn, a3[4]);
            ar[5] = fma2(u45.y, wr, ar[5]);
            az[5] = fma2(u45.y, wz, az[5]);
            a3[5] = fma2(u45.y, wn, a3[5]);
            ar[6] = fma2(u6,    wr, ar[6]);
            az[6] = fma2(u6,    wz, az[6]);
            a3[6] = fma2(u6,    wn, a3[6]);
        }
    }
}

// dynamic smem layout:
//   ush : K_*UPITCH floats      = 30720 B
//   dsh : F_*UPITCH floats      =  5120 B
//   red : 6*128*RPITCH u64      = 153600 B
//   s_emp/s_wdx/s_bdx           =    768 B
//   s_redf                      =    224 B
#define SMEM_BYTES (K_*UPITCH*4 + F_*UPITCH*4 + 6*128*RPITCH*8 + 3*F_*4 + 4*BR*4)

__global__ void __launch_bounds__(NT, 1) grud_kernel(
    const float* __restrict__ values, const float* __restrict__ masks,
    const float* __restrict__ deltas, const float* __restrict__ xlocf,
    const float* __restrict__ emp_mean, const float* __restrict__ bdh,
    const float* __restrict__ Wdx, const float* __restrict__ bdx,
    const float* __restrict__ b_ih, const float* __restrict__ b_hh,
    const float* __restrict__ Wc, const float* __restrict__ bc,
    float* __restrict__ out)
{
    extern __shared__ char smem_raw[];
    float* ush  = reinterpret_cast<float*>(smem_raw);           // [K_][UPITCH]
    float* dsh  = ush + K_*UPITCH;                              // [F_][UPITCH]
    u64*   red  = reinterpret_cast<u64*>(dsh + F_*UPITCH);      // [6][128][RPITCH]
    float* s_emp  = reinterpret_cast<float*>(red + 6*128*RPITCH);
    float* s_wdx  = s_emp + F_;
    float* s_bdx  = s_wdx + F_;
    float* s_redf = s_bdx + F_;                                  // [4][BR]

    const int tid = threadIdx.x;
    const int j   = tid & 127;   // gate/hidden column
    const int kg  = tid >> 7;    // k-group 0..5
    const int r0  = blockIdx.x * BR;

    if (tid < F_) {
        s_emp[tid] = emp_mean[tid];
        s_wdx[tid] = Wdx[tid * F_ + tid];
        s_bdx[tid] = bdx[tid];
    }
    for (int i = tid; i < K_*UPITCH; i += NT) ush[i] = 0.f;   // h0 = 0
    for (int i = tid; i < F_*UPITCH; i += NT) dsh[i] = 0.f;

    const float bdh_j = bdh[j];
    const float br_   = b_ih[j]        + b_hh[j];
    const float bz_   = b_ih[H_ + j]   + b_hh[H_ + j];
    const float bin_  = b_ih[2*H_ + j];
    const float bhn_  = b_hh[2*H_ + j];
    const float wc_j  = Wc[j];

    // stage A mapping (tid < 448): sr = local batch row, lane covers 2 features
    const int sr   = tid >> 5;           // row slot 0..13 for active threads
    const int lane = tid & 31;
    const int sf   = lane * 2;
    const int ri   = min(r0 + sr, B_ - 1);
    const size_t rowbase = (size_t)ri * T_ * F_;
    const bool aON = (tid < 448);

    // stage B mapping (tid < 512): col j, pairs 2kb, 2kb+1 (kb=3 -> pair 6 + pad 7)
    const int kb = tid >> 7;          // 0..3 valid when tid<512
    const int dp = 4 * kb;            // float offset of first owned pair

    // stage D mapping (tid < 512): col j, pairs 2pg, 2pg+1 (skip p>=7)
    const int pg = kb;

    u64* myslot = red + (size_t)((kg << 7) + j) * RPITCH;

    __syncthreads();

    // ---- prologue: stage A for t=0 ----
    if (aON) {
        const size_t base = rowbase + sf;
        float2 xv = *reinterpret_cast<const float2*>(values + base);
        float2 xm = *reinterpret_cast<const float2*>(masks  + base);
        float2 xd = *reinterpret_cast<const float2*>(deltas + base);
        float2 xl = *reinterpret_cast<const float2*>(xlocf  + base);
        float v_[2] = {xv.x, xv.y}, m_[2] = {xm.x, xm.y};
        float d_[2] = {xd.x, xd.y}, l_[2] = {xl.x, xl.y};
        #pragma unroll
        for (int q = 0; q < 2; q++) {
            int f = sf + q;
            float gx   = __expf(-fmaxf(d_[q]*s_wdx[f] + s_bdx[f], 0.f));
            float xh   = gx*l_[q] + (1.f - gx)*s_emp[f];
            float xrep = m_[q]*v_[q] + (1.f - m_[q])*xh;
            ush[f*UPITCH        + sr] = xrep;
            ush[(192+f)*UPITCH  + sr] = m_[q];
            dsh[f*UPITCH        + sr] = d_[q];
        }
    }
    __syncthreads();

    for (int t = 0; t < T_; t++) {
        // ---- B: gamma_h + h decay (tid<512; col j, pairs 2kb,2kb+1) ----
        if (tid < 512) {
            u64 acc0 = 0ull, acc1 = 0ull;
            const float4* Wd = reinterpret_cast<const float4*>(g_Wdh4);
            #pragma unroll 4
            for (int f4 = 0; f4 < F_/4; f4++) {
                float4 w = Wd[f4 * H_ + j];
                #pragma unroll
                for (int ks = 0; ks < 4; ks++) {
                    float wv = (&w.x)[ks];
                    u64 wp = pack2(wv, wv);
                    ulonglong2 dd = *reinterpret_cast<const ulonglong2*>(
                        dsh + (4*f4 + ks) * UPITCH + dp);
                    acc0 = fma2(dd.x, wp, acc0);
                    acc1 = fma2(dd.y, wp, acc1);
                }
            }
            float a0, a1, b0, b1;
            unpack2(acc0, a0, a1);
            unpack2(acc1, b0, b1);
            float g00 = __expf(-fmaxf(a0 + bdh_j, 0.f));
            float g01 = __expf(-fmaxf(a1 + bdh_j, 0.f));
            float g10 = __expf(-fmaxf(b0 + bdh_j, 0.f));
            float g11 = __expf(-fmaxf(b1 + bdh_j, 0.f));
            float* hrow = ush + (64 + j) * UPITCH;
            float h00, h01, h10, h11;
            unpack2(*reinterpret_cast<u64*>(hrow + dp),     h00, h01);
            unpack2(*reinterpret_cast<u64*>(hrow + dp + 2), h10, h11);
            u64 hd0 = pack2(h00*g00, h01*g01);
            u64 hd1 = pack2(h10*g10, h11*g11);
            *reinterpret_cast<u64*>(hrow + dp)     = hd0;
            *reinterpret_cast<u64*>(hrow + dp + 2) = hd1;
            float* hcpy = ush + (256 + j) * UPITCH;
            *reinterpret_cast<u64*>(hcpy + dp)     = hd0;
            *reinterpret_cast<u64*>(hcpy + dp + 2) = hd1;
        }
        __syncthreads();   // S1

        // ---- C: gates GEMM, 6-way k-split (16 k4 each; i/h boundary at kg=4) ----
        {
            u64 ar[NP], az[NP], a3[NP];
            #pragma unroll
            for (int p = 0; p < NP; p++) { ar[p]=0ull; az[p]=0ull; a3[p]=0ull; }
            switch (kg) {
                case 0: gemm_part< 0,16>(j, ush, ar, az, a3); break;
                case 1: gemm_part<16,32>(j, ush, ar, az, a3); break;
                case 2: gemm_part<32,48>(j, ush, ar, az, a3); break;
                case 3: gemm_part<48,64>(j, ush, ar, az, a3); break;
                case 4: gemm_part<64,80>(j, ush, ar, az, a3); break;
                default:gemm_part<80,96>(j, ush, ar, az, a3); break;
            }
            #pragma unroll
            for (int p = 0; p < NP; p++) {
                myslot[p]      = ar[p];
                myslot[7 + p]  = az[p];
                myslot[14 + p] = a3[p];
            }
        }
        __syncthreads();   // S2

        // ---- D + A(t+1): issue A's loads first, epilogue while they fly ----
        const bool doA = aON && (t + 1 < T_);
        float2 xv, xm, xd, xl;
        size_t abase = rowbase + (size_t)(t+1)*F_ + sf;
        if (doA) {
            xv = *reinterpret_cast<const float2*>(values + abase);
            xm = *reinterpret_cast<const float2*>(masks  + abase);
            xd = *reinterpret_cast<const float2*>(deltas + abase);
            xl = *reinterpret_cast<const float2*>(xlocf  + abase);
        }

        if (tid < 512) {
            float* hrow = ush + (64 + j) * UPITCH;
            #pragma unroll
            for (int pi = 0; pi < 2; pi++) {
                int p = 2*pg + pi;
                if (p >= NP) break;
                u64 rv = 0ull, zv = 0ull, iv = 0ull, hv = 0ull;
                #pragma unroll
                for (int g = 0; g < 6; g++) {
                    const u64* s = red + (size_t)((g << 7) + j) * RPITCH;
                    rv = add2(rv, s[p]);
                    zv = add2(zv, s[7 + p]);
                    u64 tv = s[14 + p];
                    if (g < 4) iv = add2(iv, tv);
                    else       hv = add2(hv, tv);
                }
                float r0f, r1f, z0f, z1f, i0f, i1f, n0f, n1f, h0f, h1f;
                unpack2(rv, r0f, r1f);
                unpack2(zv, z0f, z1f);
                unpack2(iv, i0f, i1f);
                unpack2(hv, n0f, n1f);
                unpack2(*reinterpret_cast<u64*>(hrow + 2*p), h0f, h1f);
                float rr0 = sigmoidf_(r0f + br_);
                float rr1 = sigmoidf_(r1f + br_);
                float zz0 = sigmoidf_(z0f + bz_);
                float zz1 = sigmoidf_(z1f + bz_);
                float nn0 = tanhf_(i0f + bin_ + rr0 * (n0f + bhn_));
                float nn1 = tanhf_(i1f + bin_ + rr1 * (n1f + bhn_));
                float hn0 = (1.f - zz0)*nn0 + zz0*h0f;
                float hn1 = (1.f - zz1)*nn1 + zz1*h1f;
                *reinterpret_cast<u64*>(hrow + 2*p) = pack2(hn0, hn1);
            }
        }

        if (doA) {
            float v_[2] = {xv.x, xv.y}, m_[2] = {xm.x, xm.y};
            float d_[2] = {xd.x, xd.y}, l_[2] = {xl.x, xl.y};
            #pragma unroll
            for (int q = 0; q < 2; q++) {
                int f = sf + q;
                float gx   = __expf(-fmaxf(d_[q]*s_wdx[f] + s_bdx[f], 0.f));
                float xh   = gx*l_[q] + (1.f - gx)*s_emp[f];
                float xrep = m_[q]*v_[q] + (1.f - m_[q])*xh;
                ush[f*UPITCH        + sr] = xrep;
                ush[(192+f)*UPITCH  + sr] = m_[q];
                dsh[f*UPITCH        + sr] = d_[q];
            }
        }
        __syncthreads();   // S3
    }

    // ---- final: logits = h @ Wc.T + bc ; sigmoid (first 128 threads) ----
    if (tid < 128) {
        float part[BR];
        #pragma unroll
        for (int r = 0; r < BR; r++)
            part[r] = ush[(64+j)*UPITCH + r] * wc_j;
        #pragma unroll
        for (int off = 16; off > 0; off >>= 1) {
            #pragma unroll
            for (int r = 0; r < BR; r++)
                part[r] += __shfl_down_sync(0xffffffffu, part[r], off);
        }
        if ((tid & 31) == 0) {
            int w = tid >> 5;
            #pragma unroll
            for (int r = 0; r < BR; r++) s_redf[w*BR + r] = part[r];
        }
    }
    __syncthreads();
    if (tid < BR && (r0 + tid) < B_) {
        float s = s_redf[0*BR + tid] + s_redf[1*BR + tid]
                + s_redf[2*BR + tid] + s_redf[3*BR + tid] + bc[0];
        out[r0 + tid] = sigmoidf_(s);
    }
}

extern "C" void kernel_launch(void* const* d_in, const int* in_sizes, int n_in,
                              void* d_out, int out_size) {
    const float* values   = (const float*)d_in[0];
    const float* masks    = (const float*)d_in[1];
    const float* deltas   = (const float*)d_in[2];
    const float* x_locf   = (const float*)d_in[3];
    const float* emp_mean = (const float*)d_in[4];
    const float* Wdh      = (const float*)d_in[5];
    const float* bdh      = (const float*)d_in[6];
    const float* Wdx      = (const float*)d_in[7];
    const float* bdx      = (const float*)d_in[8];
    const float* w_ih     = (const float*)d_in[9];
    const float* w_hh     = (const float*)d_in[10];
    const float* b_ih     = (const float*)d_in[11];
    const float* b_hh     = (const float*)d_in[12];
    const float* Wc       = (const float*)d_in[13];
    const float* bc       = (const float*)d_in[14];
    float* out = (float*)d_out;

    cudaFuncSetAttribute(grud_kernel,
                         cudaFuncAttributeMaxDynamicSharedMemorySize, SMEM_BYTES);

    prep_kernel<<<576, 256>>>(w_ih, w_hh, Wdh);
    grud_kernel<<<NB, NT, SMEM_BYTES>>>(values, masks, deltas, x_locf, emp_mean,
                                        bdh, Wdx, bdx, b_ih, b_hh, Wc, bc, out);
}

// round 5
// speedup vs baseline: 1.8565x; 1.1185x over previous
#include <cuda_runtime.h>
#include <cstdint>

#define B_   2048
#define T_   200
#define F_   64
#define H_   128
#define IN_  256
#define KU   256   // u rows: x_rep(64) | h(128) | m(64)
#define BR   14    // batch rows per block
#define NP   7     // row pairs
#define NT   768   // 24 warps: 128 cols x 6 k-groups
#define NB   147
#define UPITCH 20  // floats per staged row (14 used + pad, 16B-aligned rows)
#define RPITCH 25  // u64 pitch in main reduction buffer
#define HPITCH 8   // u64 pitch in hn reduction buffer

typedef unsigned long long u64;

// ---------- packed weights ----------
// g_Wrzi[k4][c][ks], c in [0,384): c<128 r-row, [128,256) z-row, [256,384) i-row.
// For c<256 the h-range (k in [64,192)) has w_hh folded in.
__device__ __align__(16) float g_Wrzi[64*384*4];
__device__ __align__(16) float g_Whn [32*128*4];   // [k4h][j][ks] = w_hh[256+j][4k4h+ks]
__device__ __align__(16) float g_Wdh4[16*128*4];   // [f4][j][ks]  = Wdh[j][4f4+ks]

__global__ void prep_kernel(const float* __restrict__ w_ih,
                            const float* __restrict__ w_hh,
                            const float* __restrict__ Wdh) {
    int idx = blockIdx.x * blockDim.x + threadIdx.x;
    int stride = gridDim.x * blockDim.x;
    const int total1 = 64*384*4;
    for (int i = idx; i < total1; i += stride) {
        int ks = i & 3;
        int c  = (i >> 2) % 384;
        int k4 = i / (4*384);
        int k  = 4*k4 + ks;
        float v = w_ih[c*IN_ + k];
        if (c < 256 && k >= 64 && k < 192) v += w_hh[c*H_ + (k - 64)];
        g_Wrzi[i] = v;
    }
    const int total2 = 32*128*4;
    for (int i = idx; i < total2; i += stride) {
        int ks = i & 3;
        int jj = (i >> 2) % 128;
        int k4 = i / (4*128);
        g_Whn[i] = w_hh[(256 + jj)*H_ + 4*k4 + ks];
    }
    const int total3 = 16*128*4;
    for (int i = idx; i < total3; i += stride) {
        int ks = i & 3;
        int jj = (i >> 2) % 128;
        int f4 = i / (4*128);
        g_Wdh4[i] = Wdh[jj*F_ + 4*f4 + ks];
    }
}

// ---------- f32x2 packed helpers ----------
__device__ __forceinline__ u64 pack2(float a, float b) {
    u64 r; asm("mov.b64 %0,{%1,%2};" : "=l"(r) : "f"(a), "f"(b)); return r;
}
__device__ __forceinline__ void unpack2(u64 v, float& a, float& b) {
    asm("mov.b64 {%0,%1},%2;" : "=f"(a), "=f"(b) : "l"(v));
}
__device__ __forceinline__ u64 fma2(u64 a, u64 b, u64 c) {
    u64 d; asm("fma.rn.f32x2 %0,%1,%2,%3;" : "=l"(d) : "l"(a), "l"(b), "l"(c)); return d;
}
__device__ __forceinline__ u64 add2(u64 a, u64 b) {
    u64 d; asm("add.rn.f32x2 %0,%1,%2;" : "=l"(d) : "l"(a), "l"(b)); return d;
}
__device__ __forceinline__ float sigmoidf_(float x) {
    return __fdividef(1.f, 1.f + __expf(-x));
}
__device__ __forceinline__ float tanhf_(float x) {
    return 1.f - __fdividef(2.f, __expf(2.f * x) + 1.f);
}

// r/z/i GEMM over N4 k4s starting at u-row base u0 and weight base wb.
template<int N4>
__device__ __forceinline__ void gemm_rzi(const float* u0, const float4* wb, int j,
                                         u64* ar, u64* az, u64* ai) {
    #pragma unroll 1
    for (int k4 = 0; k4 < N4; k4++) {
        float4 w0 = wb[k4*384 + j];
        float4 w1 = wb[k4*384 + j + 128];
        float4 w2 = wb[k4*384 + j + 256];
        #pragma unroll
        for (int ks = 0; ks < 4; ks++) {
            float f0 = (&w0.x)[ks], f1 = (&w1.x)[ks], f2 = (&w2.x)[ks];
            u64 wr = pack2(f0, f0);
            u64 wz = pack2(f1, f1);
            u64 wn = pack2(f2, f2);
            const float* ub = u0 + (4*k4 + ks) * UPITCH;
            ulonglong2 u01 = *reinterpret_cast<const ulonglong2*>(ub);
            ulonglong2 u23 = *reinterpret_cast<const ulonglong2*>(ub + 4);
            ulonglong2 u45 = *reinterpret_cast<const ulonglong2*>(ub + 8);
            u64        u6  = *reinterpret_cast<const u64*>(ub + 12);
            ar[0]=fma2(u01.x,wr,ar[0]); az[0]=fma2(u01.x,wz,az[0]); ai[0]=fma2(u01.x,wn,ai[0]);
            ar[1]=fma2(u01.y,wr,ar[1]); az[1]=fma2(u01.y,wz,az[1]); ai[1]=fma2(u01.y,wn,ai[1]);
            ar[2]=fma2(u23.x,wr,ar[2]); az[2]=fma2(u23.x,wz,az[2]); ai[2]=fma2(u23.x,wn,ai[2]);
            ar[3]=fma2(u23.y,wr,ar[3]); az[3]=fma2(u23.y,wz,az[3]); ai[3]=fma2(u23.y,wn,ai[3]);
            ar[4]=fma2(u45.x,wr,ar[4]); az[4]=fma2(u45.x,wz,az[4]); ai[4]=fma2(u45.x,wn,ai[4]);
            ar[5]=fma2(u45.y,wr,ar[5]); az[5]=fma2(u45.y,wz,az[5]); ai[5]=fma2(u45.y,wn,ai[5]);
            ar[6]=fma2(u6,   wr,ar[6]); az[6]=fma2(u6,   wz,az[6]); ai[6]=fma2(u6,   wn,ai[6]);
        }
    }
}

// h_n GEMM: 1 column, 7 pairs.
template<int N4>
__device__ __forceinline__ void gemm_hn(const float* u0, const float4* wb, int j,
                                        u64* ah) {
    #pragma unroll 1
    for (int k4 = 0; k4 < N4; k4++) {
        float4 w = wb[k4*128 + j];
        #pragma unroll
        for (int ks = 0; ks < 4; ks++) {
            float fv = (&w.x)[ks];
            u64 wn = pack2(fv, fv);
            const float* ub = u0 + (4*k4 + ks) * UPITCH;
            ulonglong2 u01 = *reinterpret_cast<const ulonglong2*>(ub);
            ulonglong2 u23 = *reinterpret_cast<const ulonglong2*>(ub + 4);
            ulonglong2 u45 = *reinterpret_cast<const ulonglong2*>(ub + 8);
            u64        u6  = *reinterpret_cast<const u64*>(ub + 12);
            ah[0]=fma2(u01.x,wn,ah[0]); ah[1]=fma2(u01.y,wn,ah[1]);
            ah[2]=fma2(u23.x,wn,ah[2]); ah[3]=fma2(u23.y,wn,ah[3]);
            ah[4]=fma2(u45.x,wn,ah[4]); ah[5]=fma2(u45.y,wn,ah[5]);
            ah[6]=fma2(u6,   wn,ah[6]);
        }
    }
}

// smem: hsh(10240) xm0/xm1(20480) ds0/ds1(10240) red(153600) redhn(16384)
//       consts(768) redf(224)  = ~211.9 KB
#define SMEM_BYTES ((128+256+128)*UPITCH*4 + 6*128*RPITCH*8 + 2*128*HPITCH*8 + 3*F_*4 + 4*BR*4)

__global__ void __launch_bounds__(NT, 1) grud_kernel(
    const float* __restrict__ values, const float* __restrict__ masks,
    const float* __restrict__ deltas, const float* __restrict__ xlocf,
    const float* __restrict__ emp_mean, const float* __restrict__ bdh,
    const float* __restrict__ Wdx, const float* __restrict__ bdx,
    const float* __restrict__ b_ih, const float* __restrict__ b_hh,
    const float* __restrict__ Wc, const float* __restrict__ bc,
    float* __restrict__ out)
{
    extern __shared__ char smem_raw[];
    float* hsh = reinterpret_cast<float*>(smem_raw);   // [128][UPITCH] : h feature j
    float* xm0 = hsh + 128*UPITCH;                     // [128][UPITCH]: x rows 0-63, m rows 64-127
    float* xm1 = xm0 + 128*UPITCH;
    float* ds0 = xm1 + 128*UPITCH;                     // [64][UPITCH]
    float* ds1 = ds0 + 64*UPITCH;
    u64*   red   = reinterpret_cast<u64*>(ds1 + 64*UPITCH);  // [6][128][RPITCH]
    u64*   redhn = red + 6*128*RPITCH;                        // [2][128][HPITCH]
    float* s_emp  = reinterpret_cast<float*>(redhn + 2*128*HPITCH);
    float* s_wdx  = s_emp + F_;
    float* s_bdx  = s_wdx + F_;
    float* s_redf = s_bdx + F_;                               // [4][BR]

    const int tid = threadIdx.x;
    const int j   = tid & 127;
    const int kg  = tid >> 7;    // 0..5
    const int r0  = blockIdx.x * BR;

    if (tid < F_) {
        s_emp[tid] = emp_mean[tid];
        s_wdx[tid] = Wdx[tid * F_ + tid];
        s_bdx[tid] = bdx[tid];
    }
    for (int i = tid; i < 128*UPITCH; i += NT) hsh[i] = 0.f;   // h0 = 0

    const float bdh_j = bdh[j];
    const float br_   = b_ih[j]        + b_hh[j];
    const float bz_   = b_ih[H_ + j]   + b_hh[H_ + j];
    const float bin_  = b_ih[2*H_ + j];
    const float bhn_  = b_hh[2*H_ + j];
    const float wc_j  = Wc[j];

    // stage A mapping (tid<448): sr = local row, lane covers 2 features
    const int sr   = tid >> 5;
    const int lane = tid & 31;
    const int sf   = lane * 2;
    const int ri   = min(r0 + sr, B_ - 1);
    const size_t rowbase = (size_t)ri * T_ * F_;
    const bool aON = (tid < 448);

    // D mapping (tid<512): col j, pairs {2kg, 2kg+1} (pair 7 invalid)
    const int dp = 4 * kg;   // float offset of first owned pair (kg<4)

    u64* myslot = red + (size_t)((kg << 7) + j) * RPITCH;
    u64* myhn   = redhn + (size_t)(((kg - 4) << 7) + j) * HPITCH;  // valid kg>=4

    const float4* Wrzi4 = reinterpret_cast<const float4*>(g_Wrzi);
    const float4* Whn4  = reinterpret_cast<const float4*>(g_Whn);

    __syncthreads();

    // ---- prologue: stage A for t=0 into buffer 0 ----
    if (aON) {
        const size_t base = rowbase + sf;
        float2 xv = *reinterpret_cast<const float2*>(values + base);
        float2 xm = *reinterpret_cast<const float2*>(masks  + base);
        float2 xd = *reinterpret_cast<const float2*>(deltas + base);
        float2 xl = *reinterpret_cast<const float2*>(xlocf  + base);
        float v_[2] = {xv.x, xv.y}, m_[2] = {xm.x, xm.y};
        float d_[2] = {xd.x, xd.y}, l_[2] = {xl.x, xl.y};
        #pragma unroll
        for (int q = 0; q < 2; q++) {
            int f = sf + q;
            float gx   = __expf(-fmaxf(d_[q]*s_wdx[f] + s_bdx[f], 0.f));
            float xh   = gx*l_[q] + (1.f - gx)*s_emp[f];
            float xrep = m_[q]*v_[q] + (1.f - m_[q])*xh;
            xm0[f*UPITCH        + sr] = xrep;
            xm0[(64+f)*UPITCH   + sr] = m_[q];
            ds0[f*UPITCH        + sr] = d_[q];
        }
    }
    __syncthreads();

    for (int t = 0; t < T_; t++) {
        const float* xmc = (t & 1) ? xm1 : xm0;   // current
        float*       xmn = (t & 1) ? xm0 : xm1;   // next
        float*       dsn = (t & 1) ? ds0 : ds1;   // delta(t+1)
        const bool doA = aON && (t + 1 < T_);

        // ---- phase 1: A(t+1) then gates GEMM ----
        if (doA) {
            const size_t base = rowbase + (size_t)(t+1)*F_ + sf;
            float2 xv = *reinterpret_cast<const float2*>(values + base);
            float2 xm = *reinterpret_cast<const float2*>(masks  + base);
            float2 xd = *reinterpret_cast<const float2*>(deltas + base);
            float2 xl = *reinterpret_cast<const float2*>(xlocf  + base);
            float v_[2] = {xv.x, xv.y}, m_[2] = {xm.x, xm.y};
            float d_[2] = {xd.x, xd.y}, l_[2] = {xl.x, xl.y};
            #pragma unroll
            for (int q = 0; q < 2; q++) {
                int f = sf + q;
                float gx   = __expf(-fmaxf(d_[q]*s_wdx[f] + s_bdx[f], 0.f));
                float xh   = gx*l_[q] + (1.f - gx)*s_emp[f];
                float xrep = m_[q]*v_[q] + (1.f - m_[q])*xh;
                xmn[f*UPITCH        + sr] = xrep;
                xmn[(64+f)*UPITCH   + sr] = m_[q];
                dsn[f*UPITCH        + sr] = d_[q];
            }
        }

        {
            u64 ar[NP], az[NP], ai[NP];
            #pragma unroll
            for (int p = 0; p < NP; p++) { ar[p]=0ull; az[p]=0ull; ai[p]=0ull; }
            switch (kg) {
                case 0:  // x k4 [0,12)
                    gemm_rzi<12>(xmc,             Wrzi4 + 0*384,  j, ar, az, ai);
                    break;
                case 1:  // x k4 [12,16) + h k4 [16,24)
                    gemm_rzi<4>(xmc + 48*UPITCH,  Wrzi4 + 12*384, j, ar, az, ai);
                    gemm_rzi<8>(hsh,              Wrzi4 + 16*384, j, ar, az, ai);
                    break;
                case 2:  // h k4 [24,36)
                    gemm_rzi<12>(hsh + 32*UPITCH, Wrzi4 + 24*384, j, ar, az, ai);
                    break;
                case 3:  // h k4 [36,48)
                    gemm_rzi<12>(hsh + 80*UPITCH, Wrzi4 + 36*384, j, ar, az, ai);
                    break;
                case 4: {  // hn k4h [0,16) then m k4 [48,56)
                    u64 ah[NP];
                    #pragma unroll
                    for (int p = 0; p < NP; p++) ah[p] = 0ull;
                    gemm_hn<16>(hsh, Whn4, j, ah);
                    #pragma unroll
                    for (int p = 0; p < NP; p++) myhn[p] = ah[p];
                    gemm_rzi<8>(xmc + 64*UPITCH,  Wrzi4 + 48*384, j, ar, az, ai);
                    break;
                }
                default: {  // hn k4h [16,32) then m k4 [56,64)
                    u64 ah[NP];
                    #pragma unroll
                    for (int p = 0; p < NP; p++) ah[p] = 0ull;
                    gemm_hn<16>(hsh + 64*UPITCH, Whn4 + 16*128, j, ah);
                    #pragma unroll
                    for (int p = 0; p < NP; p++) myhn[p] = ah[p];
                    gemm_rzi<8>(xmc + 96*UPITCH,  Wrzi4 + 56*384, j, ar, az, ai);
                    break;
                }
            }
            #pragma unroll
            for (int p = 0; p < NP; p++) {
                myslot[p]      = ar[p];
                myslot[7 + p]  = az[p];
                myslot[14 + p] = ai[p];
            }
        }
        __syncthreads();   // S1

        // ---- phase 2: reduce + epilogue + decay(t+1) (tid<512) ----
        if (tid < 512) {
            float* hrow = hsh + j*UPITCH;
            float hn_new[2][2];
            #pragma unroll
            for (int pi = 0; pi < 2; pi++) {
                int p = 2*kg + pi;
                if (p >= NP) break;
                u64 rv = 0ull, zv = 0ull, iv = 0ull;
                #pragma unroll
                for (int g = 0; g < 6; g++) {
                    const u64* s = red + (size_t)((g << 7) + j) * RPITCH;
                    rv = add2(rv, s[p]);
                    zv = add2(zv, s[7 + p]);
                    iv = add2(iv, s[14 + p]);
                }
                u64 hv = add2(redhn[(size_t)j*HPITCH + p],
                              redhn[(size_t)(128 + j)*HPITCH + p]);
                float r0f, r1f, z0f, z1f, i0f, i1f, n0f, n1f, h0f, h1f;
                unpack2(rv, r0f, r1f);
                unpack2(zv, z0f, z1f);
                unpack2(iv, i0f, i1f);
                unpack2(hv, n0f, n1f);
                unpack2(*reinterpret_cast<u64*>(hrow + 2*p), h0f, h1f);
                float rr0 = sigmoidf_(r0f + br_);
                float rr1 = sigmoidf_(r1f + br_);
                float zz0 = sigmoidf_(z0f + bz_);
                float zz1 = sigmoidf_(z1f + bz_);
                float nn0 = tanhf_(i0f + bin_ + rr0 * (n0f + bhn_));
                float nn1 = tanhf_(i1f + bin_ + rr1 * (n1f + bhn_));
                hn_new[pi][0] = (1.f - zz0)*nn0 + zz0*h0f;
                hn_new[pi][1] = (1.f - zz1)*nn1 + zz1*h1f;
            }

            if (t + 1 < T_) {
                // gamma_h for t+1 over the two owned pairs
                u64 acc0 = 0ull, acc1 = 0ull;
                const float4* Wd = reinterpret_cast<const float4*>(g_Wdh4);
                #pragma unroll 4
                for (int f4 = 0; f4 < 16; f4++) {
                    float4 w = Wd[f4*128 + j];
                    #pragma unroll
                    for (int ks = 0; ks < 4; ks++) {
                        float wv = (&w.x)[ks];
                        u64 wp = pack2(wv, wv);
                        ulonglong2 dd = *reinterpret_cast<const ulonglong2*>(
                            dsn + (4*f4 + ks) * UPITCH + dp);
                        acc0 = fma2(dd.x, wp, acc0);
                        acc1 = fma2(dd.y, wp, acc1);
                    }
                }
                float a0, a1, b0, b1;
                unpack2(acc0, a0, a1);
                unpack2(acc1, b0, b1);
                float g00 = __expf(-fmaxf(a0 + bdh_j, 0.f));
                float g01 = __expf(-fmaxf(a1 + bdh_j, 0.f));
                float g10 = __expf(-fmaxf(b0 + bdh_j, 0.f));
                float g11 = __expf(-fmaxf(b1 + bdh_j, 0.f));
                int p0 = 2*kg;
                *reinterpret_cast<u64*>(hrow + 2*p0) =
                    pack2(hn_new[0][0]*g00, hn_new[0][1]*g01);
                if (p0 + 1 < NP)
                    *reinterpret_cast<u64*>(hrow + 2*(p0+1)) =
                        pack2(hn_new[1][0]*g10, hn_new[1][1]*g11);
            } else {
                int p0 = 2*kg;
                *reinterpret_cast<u64*>(hrow + 2*p0) =
                    pack2(hn_new[0][0], hn_new[0][1]);
                if (p0 + 1 < NP)
                    *reinterpret_cast<u64*>(hrow + 2*(p0+1)) =
                        pack2(hn_new[1][0], hn_new[1][1]);
            }
        }
        __syncthreads();   // S2
    }

    // ---- final: logits = h @ Wc.T + bc ; sigmoid ----
    if (tid < 128) {
        float part[BR];
        #pragma unroll
        for (int r = 0; r < BR; r++)
            part[r] = hsh[j*UPITCH + r] * wc_j;
        #pragma unroll
        for (int off = 16; off > 0; off >>= 1) {
            #pragma unroll
            for (int r = 0; r < BR; r++)
                part[r] += __shfl_down_sync(0xffffffffu, part[r], off);
        }
        if ((tid & 31) == 0) {
            int w = tid >> 5;
            #pragma unroll
            for (int r = 0; r < BR; r++) s_redf[w*BR + r] = part[r];
        }
    }
    __syncthreads();
    if (tid < BR && (r0 + tid) < B_) {
        float s = s_redf[0*BR + tid] + s_redf[1*BR + tid]
                + s_redf[2*BR + tid] + s_redf[3*BR + tid] + bc[0];
        out[r0 + tid] = sigmoidf_(s);
    }
}

extern "C" void kernel_launch(void* const* d_in, const int* in_sizes, int n_in,
                              void* d_out, int out_size) {
    const float* values   = (const float*)d_in[0];
    const float* masks    = (const float*)d_in[1];
    const float* deltas   = (const float*)d_in[2];
    const float* x_locf   = (const float*)d_in[3];
    const float* emp_mean = (const float*)d_in[4];
    const float* Wdh      = (const float*)d_in[5];
    const float* bdh      = (const float*)d_in[6];
    const float* Wdx      = (const float*)d_in[7];
    const float* bdx      = (const float*)d_in[8];
    const float* w_ih     = (const float*)d_in[9];
    const float* w_hh     = (const float*)d_in[10];
    const float* b_ih     = (const float*)d_in[11];
    const float* b_hh     = (const float*)d_in[12];
    const float* Wc       = (const float*)d_in[13];
    const float* bc       = (const float*)d_in[14];
    float* out = (float*)d_out;

    cudaFuncSetAttribute(grud_kernel,
                         cudaFuncAttributeMaxDynamicSharedMemorySize, SMEM_BYTES);

    prep_kernel<<<576, 256>>>(w_ih, w_hh, Wdh);
    grud_kernel<<<NB, NT, SMEM_BYTES>>>(values, masks, deltas, x_locf, emp_mean,
                                        bdh, Wdx, bdx, b_ih, b_hh, Wc, bc, out);
}

// round 6
// speedup vs baseline: 1.8577x; 1.0006x over previous
#include <cuda_runtime.h>
#include <cstdint>

#define B_   2048
#define T_   200
#define F_   64
#define H_   128
#define IN_  256
#define KU   256   // u rows: x_rep(64) | h(128) | m(64)
#define BR   14    // batch rows per block
#define NP   7     // row pairs
#define NT   768   // 24 warps: 128 cols x 6 k-groups
#define NB   147
#define UPITCH 20  // floats per staged row (14 used + pad, 16B-aligned rows)
#define RPITCH 25  // u64 pitch in main reduction buffer
#define HPITCH 8   // u64 pitch in hn reduction buffer

typedef unsigned long long u64;

// ---------- packed weights ----------
// g_Wrzi[k4][c][ks], c in [0,384): c<128 r-row, [128,256) z-row, [256,384) i-row.
// For c<256 the h-range (k in [64,192)) has w_hh folded in.
__device__ __align__(16) float g_Wrzi[64*384*4];
__device__ __align__(16) float g_Whn [32*128*4];   // [k4h][j][ks] = w_hh[256+j][4k4h+ks]
__device__ __align__(16) float g_Wdh4[16*128*4];   // [f4][j][ks]  = Wdh[j][4f4+ks]

__global__ void prep_kernel(const float* __restrict__ w_ih,
                            const float* __restrict__ w_hh,
                            const float* __restrict__ Wdh) {
    int idx = blockIdx.x * blockDim.x + threadIdx.x;
    int stride = gridDim.x * blockDim.x;
    const int total1 = 64*384*4;
    for (int i = idx; i < total1; i += stride) {
        int ks = i & 3;
        int c  = (i >> 2) % 384;
        int k4 = i / (4*384);
        int k  = 4*k4 + ks;
        float v = w_ih[c*IN_ + k];
        if (c < 256 && k >= 64 && k < 192) v += w_hh[c*H_ + (k - 64)];
        g_Wrzi[i] = v;
    }
    const int total2 = 32*128*4;
    for (int i = idx; i < total2; i += stride) {
        int ks = i & 3;
        int jj = (i >> 2) % 128;
        int k4 = i / (4*128);
        g_Whn[i] = w_hh[(256 + jj)*H_ + 4*k4 + ks];
    }
    const int total3 = 16*128*4;
    for (int i = idx; i < total3; i += stride) {
        int ks = i & 3;
        int jj = (i >> 2) % 128;
        int f4 = i / (4*128);
        g_Wdh4[i] = Wdh[jj*F_ + 4*f4 + ks];
    }
}

// ---------- f32x2 packed helpers ----------
__device__ __forceinline__ u64 pack2(float a, float b) {
    u64 r; asm("mov.b64 %0,{%1,%2};" : "=l"(r) : "f"(a), "f"(b)); return r;
}
__device__ __forceinline__ void unpack2(u64 v, float& a, float& b) {
    asm("mov.b64 {%0,%1},%2;" : "=f"(a), "=f"(b) : "l"(v));
}
__device__ __forceinline__ u64 fma2(u64 a, u64 b, u64 c) {
    u64 d; asm("fma.rn.f32x2 %0,%1,%2,%3;" : "=l"(d) : "l"(a), "l"(b), "l"(c)); return d;
}
__device__ __forceinline__ u64 add2(u64 a, u64 b) {
    u64 d; asm("add.rn.f32x2 %0,%1,%2;" : "=l"(d) : "l"(a), "l"(b)); return d;
}
__device__ __forceinline__ float sigmoidf_(float x) {
    return __fdividef(1.f, 1.f + __expf(-x));
}
__device__ __forceinline__ float tanhf_(float x) {
    return 1.f - __fdividef(2.f, __expf(2.f * x) + 1.f);
}

// r/z/i GEMM over N4 k4s starting at u-row base u0 and weight base wb.
template<int N4>
__device__ __forceinline__ void gemm_rzi(const float* u0, const float4* wb, int j,
                                         u64* ar, u64* az, u64* ai) {
    #pragma unroll 1
    for (int k4 = 0; k4 < N4; k4++) {
        float4 w0 = wb[k4*384 + j];
        float4 w1 = wb[k4*384 + j + 128];
        float4 w2 = wb[k4*384 + j + 256];
        #pragma unroll
        for (int ks = 0; ks < 4; ks++) {
            float f0 = (&w0.x)[ks], f1 = (&w1.x)[ks], f2 = (&w2.x)[ks];
            u64 wr = pack2(f0, f0);
            u64 wz = pack2(f1, f1);
            u64 wn = pack2(f2, f2);
            const float* ub = u0 + (4*k4 + ks) * UPITCH;
            ulonglong2 u01 = *reinterpret_cast<const ulonglong2*>(ub);
            ulonglong2 u23 = *reinterpret_cast<const ulonglong2*>(ub + 4);
            ulonglong2 u45 = *reinterpret_cast<const ulonglong2*>(ub + 8);
            u64        u6  = *reinterpret_cast<const u64*>(ub + 12);
            ar[0]=fma2(u01.x,wr,ar[0]); az[0]=fma2(u01.x,wz,az[0]); ai[0]=fma2(u01.x,wn,ai[0]);
            ar[1]=fma2(u01.y,wr,ar[1]); az[1]=fma2(u01.y,wz,az[1]); ai[1]=fma2(u01.y,wn,ai[1]);
            ar[2]=fma2(u23.x,wr,ar[2]); az[2]=fma2(u23.x,wz,az[2]); ai[2]=fma2(u23.x,wn,ai[2]);
            ar[3]=fma2(u23.y,wr,ar[3]); az[3]=fma2(u23.y,wz,az[3]); ai[3]=fma2(u23.y,wn,ai[3]);
            ar[4]=fma2(u45.x,wr,ar[4]); az[4]=fma2(u45.x,wz,az[4]); ai[4]=fma2(u45.x,wn,ai[4]);
            ar[5]=fma2(u45.y,wr,ar[5]); az[5]=fma2(u45.y,wz,az[5]); ai[5]=fma2(u45.y,wn,ai[5]);
            ar[6]=fma2(u6,   wr,ar[6]); az[6]=fma2(u6,   wz,az[6]); ai[6]=fma2(u6,   wn,ai[6]);
        }
    }
}

// h_n GEMM: 1 column, 7 pairs.
template<int N4>
__device__ __forceinline__ void gemm_hn(const float* u0, const float4* wb, int j,
                                        u64* ah) {
    #pragma unroll 1
    for (int k4 = 0; k4 < N4; k4++) {
        float4 w = wb[k4*128 + j];
        #pragma unroll
        for (int ks = 0; ks < 4; ks++) {
            float fv = (&w.x)[ks];
            u64 wn = pack2(fv, fv);
            const float* ub = u0 + (4*k4 + ks) * UPITCH;
            ulonglong2 u01 = *reinterpret_cast<const ulonglong2*>(ub);
            ulonglong2 u23 = *reinterpret_cast<const ulonglong2*>(ub + 4);
            ulonglong2 u45 = *reinterpret_cast<const ulonglong2*>(ub + 8);
            u64        u6  = *reinterpret_cast<const u64*>(ub + 12);
            ah[0]=fma2(u01.x,wn,ah[0]); ah[1]=fma2(u01.y,wn,ah[1]);
            ah[2]=fma2(u23.x,wn,ah[2]); ah[3]=fma2(u23.y,wn,ah[3]);
            ah[4]=fma2(u45.x,wn,ah[4]); ah[5]=fma2(u45.y,wn,ah[5]);
            ah[6]=fma2(u6,   wn,ah[6]);
        }
    }
}

// smem: hsh(10240) xm0/xm1(20480) ds0/ds1(10240) red(153600) redhn(16384)
//       consts(768) redf(224)  = ~211.9 KB
#define SMEM_BYTES ((128+256+128)*UPITCH*4 + 6*128*RPITCH*8 + 2*128*HPITCH*8 + 3*F_*4 + 4*BR*4)

__global__ void __launch_bounds__(NT, 1) grud_kernel(
    const float* __restrict__ values, const float* __restrict__ masks,
    const float* __restrict__ deltas, const float* __restrict__ xlocf,
    const float* __restrict__ emp_mean, const float* __restrict__ bdh,
    const float* __restrict__ Wdx, const float* __restrict__ bdx,
    const float* __restrict__ b_ih, const float* __restrict__ b_hh,
    const float* __restrict__ Wc, const float* __restrict__ bc,
    float* __restrict__ out)
{
    extern __shared__ char smem_raw[];
    float* hsh = reinterpret_cast<float*>(smem_raw);   // [128][UPITCH] : h feature j
    float* xm0 = hsh + 128*UPITCH;                     // [128][UPITCH]: x rows 0-63, m rows 64-127
    float* xm1 = xm0 + 128*UPITCH;
    float* ds0 = xm1 + 128*UPITCH;                     // [64][UPITCH]
    float* ds1 = ds0 + 64*UPITCH;
    u64*   red   = reinterpret_cast<u64*>(ds1 + 64*UPITCH);  // [6][128][RPITCH]
    u64*   redhn = red + 6*128*RPITCH;                        // [2][128][HPITCH]
    float* s_emp  = reinterpret_cast<float*>(redhn + 2*128*HPITCH);
    float* s_wdx  = s_emp + F_;
    float* s_bdx  = s_wdx + F_;
    float* s_redf = s_bdx + F_;                               // [4][BR]

    const int tid = threadIdx.x;
    const int j   = tid & 127;
    const int kg  = tid >> 7;    // 0..5
    const int r0  = blockIdx.x * BR;

    if (tid < F_) {
        s_emp[tid] = emp_mean[tid];
        s_wdx[tid] = Wdx[tid * F_ + tid];
        s_bdx[tid] = bdx[tid];
    }
    for (int i = tid; i < 128*UPITCH; i += NT) hsh[i] = 0.f;   // h0 = 0

    const float bdh_j = bdh[j];
    const float br_   = b_ih[j]        + b_hh[j];
    const float bz_   = b_ih[H_ + j]   + b_hh[H_ + j];
    const float bin_  = b_ih[2*H_ + j];
    const float bhn_  = b_hh[2*H_ + j];
    const float wc_j  = Wc[j];

    // stage A mapping (tid<448): sr = local row, lane covers 2 features
    const int sr   = tid >> 5;
    const int lane = tid & 31;
    const int sf   = lane * 2;
    const int ri   = min(r0 + sr, B_ - 1);
    const size_t rowbase = (size_t)ri * T_ * F_;
    const bool aON = (tid < 448);

    // D mapping (tid<512): col j, pairs {2kg, 2kg+1} (pair 7 invalid)
    const int dp = 4 * kg;   // float offset of first owned pair (kg<4)

    u64* myslot = red + (size_t)((kg << 7) + j) * RPITCH;
    u64* myhn   = redhn + (size_t)(((kg - 4) << 7) + j) * HPITCH;  // valid kg>=4

    const float4* Wrzi4 = reinterpret_cast<const float4*>(g_Wrzi);
    const float4* Whn4  = reinterpret_cast<const float4*>(g_Whn);

    __syncthreads();

    // ---- prologue: stage A for t=0 into buffer 0 ----
    if (aON) {
        const size_t base = rowbase + sf;
        float2 xv = *reinterpret_cast<const float2*>(values + base);
        float2 xm = *reinterpret_cast<const float2*>(masks  + base);
        float2 xd = *reinterpret_cast<const float2*>(deltas + base);
        float2 xl = *reinterpret_cast<const float2*>(xlocf  + base);
        float v_[2] = {xv.x, xv.y}, m_[2] = {xm.x, xm.y};
        float d_[2] = {xd.x, xd.y}, l_[2] = {xl.x, xl.y};
        #pragma unroll
        for (int q = 0; q < 2; q++) {
            int f = sf + q;
            float gx   = __expf(-fmaxf(d_[q]*s_wdx[f] + s_bdx[f], 0.f));
            float xh   = gx*l_[q] + (1.f - gx)*s_emp[f];
            float xrep = m_[q]*v_[q] + (1.f - m_[q])*xh;
            xm0[f*UPITCH        + sr] = xrep;
            xm0[(64+f)*UPITCH   + sr] = m_[q];
            ds0[f*UPITCH        + sr] = d_[q];
        }
    }
    __syncthreads();

    for (int t = 0; t < T_; t++) {
        const float* xmc = (t & 1) ? xm1 : xm0;   // current
        float*       xmn = (t & 1) ? xm0 : xm1;   // next
        float*       dsn = (t & 1) ? ds0 : ds1;   // delta(t+1)
        const bool doA = aON && (t + 1 < T_);

        // ---- phase 1: A(t+1) then gates GEMM ----
        if (doA) {
            const size_t base = rowbase + (size_t)(t+1)*F_ + sf;
            float2 xv = *reinterpret_cast<const float2*>(values + base);
            float2 xm = *reinterpret_cast<const float2*>(masks  + base);
            float2 xd = *reinterpret_cast<const float2*>(deltas + base);
            float2 xl = *reinterpret_cast<const float2*>(xlocf  + base);
            float v_[2] = {xv.x, xv.y}, m_[2] = {xm.x, xm.y};
            float d_[2] = {xd.x, xd.y}, l_[2] = {xl.x, xl.y};
            #pragma unroll
            for (int q = 0; q < 2; q++) {
                int f = sf + q;
                float gx   = __expf(-fmaxf(d_[q]*s_wdx[f] + s_bdx[f], 0.f));
                float xh   = gx*l_[q] + (1.f - gx)*s_emp[f];
                float xrep = m_[q]*v_[q] + (1.f - m_[q])*xh;
                xmn[f*UPITCH        + sr] = xrep;
                xmn[(64+f)*UPITCH   + sr] = m_[q];
                dsn[f*UPITCH        + sr] = d_[q];
            }
        }

        {
            u64 ar[NP], az[NP], ai[NP];
            #pragma unroll
            for (int p = 0; p < NP; p++) { ar[p]=0ull; az[p]=0ull; ai[p]=0ull; }
            switch (kg) {
                case 0:  // x k4 [0,12)
                    gemm_rzi<12>(xmc,             Wrzi4 + 0*384,  j, ar, az, ai);
                    break;
                case 1:  // x k4 [12,16) + h k4 [16,24)
                    gemm_rzi<4>(xmc + 48*UPITCH,  Wrzi4 + 12*384, j, ar, az, ai);
                    gemm_rzi<8>(hsh,              Wrzi4 + 16*384, j, ar, az, ai);
                    break;
                case 2:  // h k4 [24,36)
                    gemm_rzi<12>(hsh + 32*UPITCH, Wrzi4 + 24*384, j, ar, az, ai);
                    break;
                case 3:  // h k4 [36,48)
                    gemm_rzi<12>(hsh + 80*UPITCH, Wrzi4 + 36*384, j, ar, az, ai);
                    break;
                case 4: {  // hn k4h [0,16) then m k4 [48,56)
                    u64 ah[NP];
                    #pragma unroll
                    for (int p = 0; p < NP; p++) ah[p] = 0ull;
                    gemm_hn<16>(hsh, Whn4, j, ah);
                    #pragma unroll
                    for (int p = 0; p < NP; p++) myhn[p] = ah[p];
                    gemm_rzi<8>(xmc + 64*UPITCH,  Wrzi4 + 48*384, j, ar, az, ai);
                    break;
                }
                default: {  // hn k4h [16,32) then m k4 [56,64)
                    u64 ah[NP];
                    #pragma unroll
                    for (int p = 0; p < NP; p++) ah[p] = 0ull;
                    gemm_hn<16>(hsh + 64*UPITCH, Whn4 + 16*128, j, ah);
                    #pragma unroll
                    for (int p = 0; p < NP; p++) myhn[p] = ah[p];
                    gemm_rzi<8>(xmc + 96*UPITCH,  Wrzi4 + 56*384, j, ar, az, ai);
                    break;
                }
            }
            #pragma unroll
            for (int p = 0; p < NP; p++) {
                myslot[p]      = ar[p];
                myslot[7 + p]  = az[p];
                myslot[14 + p] = ai[p];
            }
        }
        __syncthreads();   // S1

        // ---- phase 2: reduce + epilogue + decay(t+1) (tid<512) ----
        if (tid < 512) {
            float* hrow = hsh + j*UPITCH;
            float hn_new[2][2];
            #pragma unroll
            for (int pi = 0; pi < 2; pi++) {
                int p = 2*kg + pi;
                if (p >= NP) break;
                u64 rv = 0ull, zv = 0ull, iv = 0ull;
                #pragma unroll
                for (int g = 0; g < 6; g++) {
                    const u64* s = red + (size_t)((g << 7) + j) * RPITCH;
                    rv = add2(rv, s[p]);
                    zv = add2(zv, s[7 + p]);
                    iv = add2(iv, s[14 + p]);
                }
                u64 hv = add2(redhn[(size_t)j*HPITCH + p],
                              redhn[(size_t)(128 + j)*HPITCH + p]);
                float r0f, r1f, z0f, z1f, i0f, i1f, n0f, n1f, h0f, h1f;
                unpack2(rv, r0f, r1f);
                unpack2(zv, z0f, z1f);
                unpack2(iv, i0f, i1f);
                unpack2(hv, n0f, n1f);
                unpack2(*reinterpret_cast<u64*>(hrow + 2*p), h0f, h1f);
                float rr0 = sigmoidf_(r0f + br_);
                float rr1 = sigmoidf_(r1f + br_);
                float zz0 = sigmoidf_(z0f + bz_);
                float zz1 = sigmoidf_(z1f + bz_);
                float nn0 = tanhf_(i0f + bin_ + rr0 * (n0f + bhn_));
                float nn1 = tanhf_(i1f + bin_ + rr1 * (n1f + bhn_));
                hn_new[pi][0] = (1.f - zz0)*nn0 + zz0*h0f;
                hn_new[pi][1] = (1.f - zz1)*nn1 + zz1*h1f;
            }

            if (t + 1 < T_) {
                // gamma_h for t+1 over the two owned pairs
                u64 acc0 = 0ull, acc1 = 0ull;
                const float4* Wd = reinterpret_cast<const float4*>(g_Wdh4);
                #pragma unroll 4
                for (int f4 = 0; f4 < 16; f4++) {
                    float4 w = Wd[f4*128 + j];
                    #pragma unroll
                    for (int ks = 0; ks < 4; ks++) {
                        float wv = (&w.x)[ks];
                        u64 wp = pack2(wv, wv);
                        ulonglong2 dd = *reinterpret_cast<const ulonglong2*>(
                            dsn + (4*f4 + ks) * UPITCH + dp);
                        acc0 = fma2(dd.x, wp, acc0);
                        acc1 = fma2(dd.y, wp, acc1);
                    }
                }
                float a0, a1, b0, b1;
                unpack2(acc0, a0, a1);
                unpack2(acc1, b0, b1);
                float g00 = __expf(-fmaxf(a0 + bdh_j, 0.f));
                float g01 = __expf(-fmaxf(a1 + bdh_j, 0.f));
                float g10 = __expf(-fmaxf(b0 + bdh_j, 0.f));
                float g11 = __expf(-fmaxf(b1 + bdh_j, 0.f));
                int p0 = 2*kg;
                *reinterpret_cast<u64*>(hrow + 2*p0) =
                    pack2(hn_new[0][0]*g00, hn_new[0][1]*g01);
                if (p0 + 1 < NP)
                    *reinterpret_cast<u64*>(hrow + 2*(p0+1)) =
                        pack2(hn_new[1][0]*g10, hn_new[1][1]*g11);
            } else {
                int p0 = 2*kg;
                *reinterpret_cast<u64*>(hrow + 2*p0) =
                    pack2(hn_new[0][0], hn_new[0][1]);
                if (p0 + 1 < NP)
                    *reinterpret_cast<u64*>(hrow + 2*(p0+1)) =
                        pack2(hn_new[1][0], hn_new[1][1]);
            }
        }
        __syncthreads();   // S2
    }

    // ---- final: logits = h @ Wc.T + bc ; sigmoid ----
    if (tid < 128) {
        float part[BR];
        #pragma unroll
        for (int r = 0; r < BR; r++)
            part[r] = hsh[j*UPITCH + r] * wc_j;
        #pragma unroll
        for (int off = 16; off > 0; off >>= 1) {
            #pragma unroll
            for (int r = 0; r < BR; r++)
                part[r] += __shfl_down_sync(0xffffffffu, part[r], off);
        }
        if ((tid & 31) == 0) {
            int w = tid >> 5;
            #pragma unroll
            for (int r = 0; r < BR; r++) s_redf[w*BR + r] = part[r];
        }
    }
    __syncthreads();
    if (tid < BR && (r0 + tid) < B_) {
        float s = s_redf[0*BR + tid] + s_redf[1*BR + tid]
                + s_redf[2*BR + tid] + s_redf[3*BR + tid] + bc[0];
        out[r0 + tid] = sigmoidf_(s);
    }
}

extern "C" void kernel_launch(void* const* d_in, const int* in_sizes, int n_in,
                              void* d_out, int out_size) {
    const float* values   = (const float*)d_in[0];
    const float* masks    = (const float*)d_in[1];
    const float* deltas   = (const float*)d_in[2];
    const float* x_locf   = (const float*)d_in[3];
    const float* emp_mean = (const float*)d_in[4];
    const float* Wdh      = (const float*)d_in[5];
    const float* bdh      = (const float*)d_in[6];
    const float* Wdx      = (const float*)d_in[7];
    const float* bdx      = (const float*)d_in[8];
    const float* w_ih     = (const float*)d_in[9];
    const float* w_hh     = (const float*)d_in[10];
    const float* b_ih     = (const float*)d_in[11];
    const float* b_hh     = (const float*)d_in[12];
    const float* Wc       = (const float*)d_in[13];
    const float* bc       = (const float*)d_in[14];
    float* out = (float*)d_out;

    cudaFuncSetAttribute(grud_kernel,
                         cudaFuncAttributeMaxDynamicSharedMemorySize, SMEM_BYTES);

    prep_kernel<<<576, 256>>>(w_ih, w_hh, Wdh);
    grud_kernel<<<NB, NT, SMEM_BYTES>>>(values, masks, deltas, x_locf, emp_mean,
                                        bdh, Wdx, bdx, b_ih, b_hh, Wc, bc, out);
}